// round 2
// baseline (speedup 1.0000x reference)
#include <cuda_runtime.h>
#include <cstdint>
#include <cstddef>

// Problem constants
// B=4, N=8192, DIN=512, DINNER=512, DOUT=512, W=128  -> 64 windows/batch, pad=0
#define MTOT 32768              // B*N rows

// Scratch (alloc-guard-safe: __device__ globals)
__device__ float g_qk[(size_t)MTOT * 1024];   // [m][0:512]=Q, [m][512:1024]=K   (128 MB)
__device__ float g_att[(size_t)MTOT * 512];   // attention output                 (64 MB)

// ---------------------------------------------------------------------------
// C[M,Nc] = A[M,K] @ B[Nc,K]^T (+ bias), all row-major. M%128==0, Nc%128==0, K%8==0.
// 128x128 tile, BK=8, 256 threads, 8x8 micro-tile.
// ---------------------------------------------------------------------------
__global__ __launch_bounds__(256)
void sgemm_nt_kernel(const float* __restrict__ A, const float* __restrict__ Bm,
                     const float* __restrict__ bias, float* __restrict__ C,
                     int M, int Nc, int K)
{
    constexpr int BM = 128, BN = 128, BK = 8, PADM = 132;
    __shared__ float As[BK * PADM];
    __shared__ float Bs[BK * PADM];

    const int tid = threadIdx.x;
    const int bx = blockIdx.x, by = blockIdx.y;
    const float* Ab = A + (size_t)by * BM * K;
    const float* Bb = Bm + (size_t)bx * BN * K;

    const int lrow = tid >> 1;          // 0..127
    const int lcol = (tid & 1) * 4;     // 0 or 4
    const int tx = tid & 15;            // 0..15 -> cols tx*8
    const int ty = tid >> 4;            // 0..15 -> rows ty*8

    float acc[8][8];
#pragma unroll
    for (int i = 0; i < 8; i++)
#pragma unroll
        for (int j = 0; j < 8; j++) acc[i][j] = 0.f;

    for (int k0 = 0; k0 < K; k0 += BK) {
        float4 av = *(const float4*)(Ab + (size_t)lrow * K + k0 + lcol);
        float4 bv = *(const float4*)(Bb + (size_t)lrow * K + k0 + lcol);
        As[(lcol + 0) * PADM + lrow] = av.x;
        As[(lcol + 1) * PADM + lrow] = av.y;
        As[(lcol + 2) * PADM + lrow] = av.z;
        As[(lcol + 3) * PADM + lrow] = av.w;
        Bs[(lcol + 0) * PADM + lrow] = bv.x;
        Bs[(lcol + 1) * PADM + lrow] = bv.y;
        Bs[(lcol + 2) * PADM + lrow] = bv.z;
        Bs[(lcol + 3) * PADM + lrow] = bv.w;
        __syncthreads();

#pragma unroll
        for (int kk = 0; kk < BK; kk++) {
            float a8[8], b8[8];
#pragma unroll
            for (int i = 0; i < 8; i++) a8[i] = As[kk * PADM + ty * 8 + i];
#pragma unroll
            for (int j = 0; j < 8; j++) b8[j] = Bs[kk * PADM + tx * 8 + j];
#pragma unroll
            for (int i = 0; i < 8; i++)
#pragma unroll
                for (int j = 0; j < 8; j++) acc[i][j] += a8[i] * b8[j];
        }
        __syncthreads();
    }

    float bv8[8];
#pragma unroll
    for (int j = 0; j < 8; j++)
        bv8[j] = bias ? bias[bx * BN + tx * 8 + j] : 0.f;

#pragma unroll
    for (int i = 0; i < 8; i++) {
        size_t row = (size_t)by * BM + ty * 8 + i;
        float* Cp = C + row * Nc + bx * BN + tx * 8;
        float4 o0 = make_float4(acc[i][0] + bv8[0], acc[i][1] + bv8[1],
                                acc[i][2] + bv8[2], acc[i][3] + bv8[3]);
        float4 o1 = make_float4(acc[i][4] + bv8[4], acc[i][5] + bv8[5],
                                acc[i][6] + bv8[6], acc[i][7] + bv8[7]);
        *(float4*)Cp = o0;
        *(float4*)(Cp + 4) = o1;
    }
}

// ---------------------------------------------------------------------------
// Windowed attention. Grid: B * 64 windows * 2 halves = 512 blocks, 256 thr.
// Each block: 64 queries x 256 keys (prev window [zeros if wb==0] + current),
// softmax with causal mask (col <= qi+128; zero-bucket cols are NOT masked),
// then O = P @ K2 (reference bug: V := K).
// ---------------------------------------------------------------------------
__global__ __launch_bounds__(256)
void attn_kernel(const float* __restrict__ qk, float* __restrict__ outa)
{
    constexpr int SP  = 260;   // S row pitch (conflict-free softmax, keeps f4 align)
    constexpr int KSP = 260;   // Ks/Vs row pitch
    constexpr int QSP = 68;    // Qs row pitch

    extern __shared__ float sm[];
    float* S  = sm;                    // 64 * 260
    float* Qs = sm + 64 * SP;          // 16 * 68
    float* Ks = Qs + 16 * QSP;         // 16 * 260
    float* Vs = Qs;                    // phase-2 reuse of Qs+Ks region (4160 <= 5248)

    const int tid  = threadIdx.x;
    const int z    = blockIdx.x;
    const int b    = z >> 7;           // batch
    const int r    = z & 127;
    const int wb   = r >> 1;           // window
    const int half = r & 1;            // 64-row half of the window

    const float* qbase = qk + ((size_t)(b * 8192 + wb * 128 + half * 64)) * 1024;
    const int kn0 = wb * 128 - 128;    // global n of key row j=0 (may be negative)

    const int ty = tid >> 5;           // 0..7  (warp id) -> rows ty*8..+7
    const int tx = tid & 31;           // lane  -> cols tx*8..+7

    // ---- Phase 1: S = Q @ K2^T -------------------------------------------
    const int qlr = tid >> 2;          // 0..63
    const int qlc = (tid & 3) * 4;     // 0,4,8,12

    float acc[8][8];
#pragma unroll
    for (int i = 0; i < 8; i++)
#pragma unroll
        for (int j = 0; j < 8; j++) acc[i][j] = 0.f;

    for (int k0 = 0; k0 < 512; k0 += 16) {
        // Q chunk: 64 rows x 16 cols
        float4 qv = *(const float4*)(qbase + (size_t)qlr * 1024 + k0 + qlc);
        Qs[(qlc + 0) * QSP + qlr] = qv.x;
        Qs[(qlc + 1) * QSP + qlr] = qv.y;
        Qs[(qlc + 2) * QSP + qlr] = qv.z;
        Qs[(qlc + 3) * QSP + qlr] = qv.w;
        // K chunk: 256 rows x 16 cols (zeros for n<0)
#pragma unroll
        for (int rr = 0; rr < 4; rr++) {
            int row = qlr + rr * 64;
            int n = kn0 + row;
            float4 kv = make_float4(0.f, 0.f, 0.f, 0.f);
            if (n >= 0)
                kv = *(const float4*)(qk + ((size_t)b * 8192 + n) * 1024 + 512 + k0 + qlc);
            Ks[(qlc + 0) * KSP + row] = kv.x;
            Ks[(qlc + 1) * KSP + row] = kv.y;
            Ks[(qlc + 2) * KSP + row] = kv.z;
            Ks[(qlc + 3) * KSP + row] = kv.w;
        }
        __syncthreads();

#pragma unroll
        for (int kk = 0; kk < 16; kk++) {
            float a8[8], b8[8];
#pragma unroll
            for (int i = 0; i < 8; i++) a8[i] = Qs[kk * QSP + ty * 8 + i];
#pragma unroll
            for (int j = 0; j < 8; j++) b8[j] = Ks[kk * KSP + tx * 8 + j];
#pragma unroll
            for (int i = 0; i < 8; i++)
#pragma unroll
                for (int j = 0; j < 8; j++) acc[i][j] += a8[i] * b8[j];
        }
        __syncthreads();
    }

    // scale + mask + stage S in smem
    const float scale = 0.044194173824159216f;   // 512^-0.5
#pragma unroll
    for (int i = 0; i < 8; i++) {
        int lr = ty * 8 + i;              // 0..63
        int qi = half * 64 + lr;          // window-local query index 0..127
#pragma unroll
        for (int j = 0; j < 8; j++) {
            int col = tx * 8 + j;
            float v = acc[i][j] * scale;
            if (col > qi + 128) v = -1e30f;   // masked -> softmax prob exactly 0
            S[lr * SP + col] = v;
        }
    }
    __syncthreads();

    // ---- Softmax over 256 cols, 4 threads per row --------------------------
    {
        int row = tid >> 2;
        int l4  = tid & 3;
        float m = -1e30f;
        for (int c = l4; c < 256; c += 4) m = fmaxf(m, S[row * SP + c]);
        m = fmaxf(m, __shfl_xor_sync(0xffffffffu, m, 1));
        m = fmaxf(m, __shfl_xor_sync(0xffffffffu, m, 2));
        float s = 0.f;
        for (int c = l4; c < 256; c += 4) {
            float e = __expf(S[row * SP + c] - m);
            S[row * SP + c] = e;
            s += e;
        }
        s += __shfl_xor_sync(0xffffffffu, s, 1);
        s += __shfl_xor_sync(0xffffffffu, s, 2);
        float inv = 1.f / s;
        for (int c = l4; c < 256; c += 4) S[row * SP + c] *= inv;
    }
    __syncthreads();

    // ---- Phase 2: O = P @ K2 (V:=K per reference bug) -----------------------
    float* outbase = outa + ((size_t)(b * 8192 + wb * 128 + half * 64)) * 512;

    for (int d0 = 0; d0 < 512; d0 += 256) {
        float acc2[8][8];
#pragma unroll
        for (int i = 0; i < 8; i++)
#pragma unroll
            for (int j = 0; j < 8; j++) acc2[i][j] = 0.f;

        for (int j0 = 0; j0 < 256; j0 += 16) {
            // V chunk: rows j0..j0+15, cols d0..d0+255 (16 floats / thread)
            int vr  = tid >> 4;            // 0..15
            int vcb = (tid & 15) * 16;     // 0..240
            int n = kn0 + j0 + vr;
#pragma unroll
            for (int u = 0; u < 4; u++) {
                float4 vv = make_float4(0.f, 0.f, 0.f, 0.f);
                if (n >= 0)
                    vv = *(const float4*)(qk + ((size_t)b * 8192 + n) * 1024 + 512 + d0 + vcb + u * 4);
                Vs[vr * KSP + vcb + u * 4 + 0] = vv.x;
                Vs[vr * KSP + vcb + u * 4 + 1] = vv.y;
                Vs[vr * KSP + vcb + u * 4 + 2] = vv.z;
                Vs[vr * KSP + vcb + u * 4 + 3] = vv.w;
            }
            __syncthreads();

#pragma unroll
            for (int kk = 0; kk < 16; kk++) {
                float p8[8], v8[8];
#pragma unroll
                for (int i = 0; i < 8; i++) p8[i] = S[(ty * 8 + i) * SP + j0 + kk];
#pragma unroll
                for (int c = 0; c < 8; c++) v8[c] = Vs[kk * KSP + tx * 8 + c];
#pragma unroll
                for (int i = 0; i < 8; i++)
#pragma unroll
                    for (int c = 0; c < 8; c++) acc2[i][c] += p8[i] * v8[c];
            }
            __syncthreads();
        }

#pragma unroll
        for (int i = 0; i < 8; i++) {
            float* op = outbase + (size_t)(ty * 8 + i) * 512 + d0 + tx * 8;
            *(float4*)op       = make_float4(acc2[i][0], acc2[i][1], acc2[i][2], acc2[i][3]);
            *(float4*)(op + 4) = make_float4(acc2[i][4], acc2[i][5], acc2[i][6], acc2[i][7]);
        }
    }
}

// ---------------------------------------------------------------------------
extern "C" void kernel_launch(void* const* d_in, const int* in_sizes, int n_in,
                              void* d_out, int out_size)
{
    const float* x     = (const float*)d_in[0];   // (4, 8192, 512)
    const float* w_qkv = (const float*)d_in[1];   // (1536, 512) — rows 1024:1536 dead (ref bug)
    const float* w_out = (const float*)d_in[2];   // (512, 512)
    const float* b_out = (const float*)d_in[3];   // (512,)
    float* out = (float*)d_out;                   // (4, 8192, 512) fp32

    float* qkbuf  = nullptr;
    float* attbuf = nullptr;
    cudaGetSymbolAddress((void**)&qkbuf,  g_qk);
    cudaGetSymbolAddress((void**)&attbuf, g_att);

    const int attn_smem = (64 * 260 + 16 * 68 + 16 * 260) * 4;   // 87552 B
    cudaFuncSetAttribute(attn_kernel, cudaFuncAttributeMaxDynamicSharedMemorySize, attn_smem);

    // 1) Q,K projection: [32768,512] @ [1024,512]^T -> g_qk
    dim3 g1(1024 / 128, MTOT / 128);
    sgemm_nt_kernel<<<g1, 256>>>(x, w_qkv, nullptr, qkbuf, MTOT, 1024, 512);

    // 2) Windowed attention (V := K per reference) -> g_att
    attn_kernel<<<512, 256, attn_smem>>>(qkbuf, attbuf);

    // 3) Output projection + bias: [32768,512] @ [512,512]^T -> out
    dim3 g3(512 / 128, MTOT / 128);
    sgemm_nt_kernel<<<g3, 256>>>(attbuf, w_out, b_out, out, MTOT, 512, 512);
}

// round 3
// speedup vs baseline: 2.9946x; 2.9946x over previous
#include <cuda_runtime.h>
#include <cstdint>
#include <cstddef>

// B=4, N=8192, DIN=512, DINNER=512, DOUT=512, W=128 -> 64 windows/batch, pad=0
#define MTOT 32768

// Scratch (alloc-guard-safe __device__ globals)
__device__ float g_qk[(size_t)MTOT * 1024];   // [m][0:512]=Q, [m][512:1024]=K
__device__ float g_att[(size_t)MTOT * 512];   // attention output

__device__ __forceinline__ unsigned f2tf(float x) {
    unsigned r; asm("cvt.rna.tf32.f32 %0, %1;" : "=r"(r) : "f"(x)); return r;
}
__device__ __forceinline__ void mma8(float* c, unsigned a0, unsigned a1, unsigned a2, unsigned a3,
                                     unsigned b0, unsigned b1) {
    asm volatile("mma.sync.aligned.m16n8k8.row.col.f32.tf32.tf32.f32 "
                 "{%0,%1,%2,%3}, {%4,%5,%6,%7}, {%8,%9}, {%0,%1,%2,%3};"
                 : "+f"(c[0]), "+f"(c[1]), "+f"(c[2]), "+f"(c[3])
                 : "r"(a0), "r"(a1), "r"(a2), "r"(a3), "r"(b0), "r"(b1));
}

// ---------------------------------------------------------------------------
// C[M,Nc] = A[M,K] @ B[Nc,K]^T (+bias). tf32 mma, 128x128x32 tiles, dbl-buffered.
// 8 warps as 4(m) x 2(n); warp tile 32x64; fragment m16n8k8.
// ---------------------------------------------------------------------------
__global__ __launch_bounds__(256)
void gemm_tf32(const float* __restrict__ A, const float* __restrict__ Bm,
               const float* __restrict__ bias, float* __restrict__ C,
               int M, int Nc, int K)
{
    extern __shared__ float sh[];
    float* As = sh;              // 2 buffers * 128*36
    float* Bs = sh + 2 * 128 * 36;

    const int tid = threadIdx.x;
    const int lane = tid & 31, wid = tid >> 5;
    const int g = lane >> 2, tg = lane & 3;
    const int wm = (wid >> 1) * 32;
    const int wn = (wid & 1) * 64;
    const float* Ab = A + (size_t)blockIdx.y * 128 * K;
    const float* Bb = Bm + (size_t)blockIdx.x * 128 * K;
    const int lr = tid >> 3, lc = (tid & 7) * 4;

    float acc[2][8][4];
#pragma unroll
    for (int mt = 0; mt < 2; mt++)
#pragma unroll
        for (int nt = 0; nt < 8; nt++)
#pragma unroll
            for (int q = 0; q < 4; q++) acc[mt][nt][q] = 0.f;

    float4 ra[4], rb[4];
    auto ldtile = [&](int k0) {
#pragma unroll
        for (int it = 0; it < 4; it++) {
            ra[it] = *(const float4*)(Ab + (size_t)(lr + it * 32) * K + k0 + lc);
            rb[it] = *(const float4*)(Bb + (size_t)(lr + it * 32) * K + k0 + lc);
        }
    };
    auto sttile = [&](int buf) {
        float* Ad = As + buf * 4608;
        float* Bd = Bs + buf * 4608;
#pragma unroll
        for (int it = 0; it < 4; it++) {
            int base = (lr + it * 32) * 36 + lc;
            Ad[base + 0] = __uint_as_float(f2tf(ra[it].x));
            Ad[base + 1] = __uint_as_float(f2tf(ra[it].y));
            Ad[base + 2] = __uint_as_float(f2tf(ra[it].z));
            Ad[base + 3] = __uint_as_float(f2tf(ra[it].w));
            Bd[base + 0] = __uint_as_float(f2tf(rb[it].x));
            Bd[base + 1] = __uint_as_float(f2tf(rb[it].y));
            Bd[base + 2] = __uint_as_float(f2tf(rb[it].z));
            Bd[base + 3] = __uint_as_float(f2tf(rb[it].w));
        }
    };
    auto compute = [&](int buf) {
        const float* Ac = As + buf * 4608;
        const float* Bc = Bs + buf * 4608;
#pragma unroll
        for (int ks = 0; ks < 4; ks++) {
            const int kk = ks * 8;
            unsigned af[2][4];
#pragma unroll
            for (int mt = 0; mt < 2; mt++) {
                int r0 = (wm + mt * 16 + g) * 36 + kk + tg;
                af[mt][0] = __float_as_uint(Ac[r0]);
                af[mt][1] = __float_as_uint(Ac[r0 + 8 * 36]);
                af[mt][2] = __float_as_uint(Ac[r0 + 4]);
                af[mt][3] = __float_as_uint(Ac[r0 + 8 * 36 + 4]);
            }
#pragma unroll
            for (int nt = 0; nt < 8; nt++) {
                int r0 = (wn + nt * 8 + g) * 36 + kk + tg;
                unsigned b0 = __float_as_uint(Bc[r0]);
                unsigned b1 = __float_as_uint(Bc[r0 + 4]);
#pragma unroll
                for (int mt = 0; mt < 2; mt++)
                    mma8(acc[mt][nt], af[mt][0], af[mt][1], af[mt][2], af[mt][3], b0, b1);
            }
        }
    };

    ldtile(0); sttile(0); __syncthreads();
    const int T = K / 32;
    for (int t = 0; t < T; t++) {
        if (t + 1 < T) ldtile((t + 1) * 32);
        compute(t & 1);
        if (t + 1 < T) sttile((t + 1) & 1);
        __syncthreads();
    }

#pragma unroll
    for (int mt = 0; mt < 2; mt++) {
        int row = blockIdx.y * 128 + wm + mt * 16 + g;
#pragma unroll
        for (int nt = 0; nt < 8; nt++) {
            int col = blockIdx.x * 128 + wn + nt * 8 + tg * 2;
            float b0 = 0.f, b1 = 0.f;
            if (bias) { b0 = bias[col]; b1 = bias[col + 1]; }
            *(float2*)(C + (size_t)row * Nc + col) =
                make_float2(acc[mt][nt][0] + b0, acc[mt][nt][1] + b1);
            *(float2*)(C + (size_t)(row + 8) * Nc + col) =
                make_float2(acc[mt][nt][2] + b0, acc[mt][nt][3] + b1);
        }
    }
}

// ---------------------------------------------------------------------------
// Windowed attention (tf32 mma). 512 blocks: b * 64 windows * 2 half-windows.
// Per block: 64 queries x 256 keys (prev window [zeros if wb==0] + current),
// causal mask col <= qi+128, softmax, O = P @ K2 (reference bug: V := K).
// ---------------------------------------------------------------------------
__global__ __launch_bounds__(256)
void attn_tf32(const float* __restrict__ qk, float* __restrict__ outa)
{
    extern __shared__ float sh[];
    float* S = sh;                 // 64 * 260 (pitch 260 % 32 == 4 -> frag-conflict-free)
    float* U = sh + 64 * 260;      // union: ph1 Q/K dbl-buf (2*11520) | ph2 V dbl-buf (2*8448)

    const int tid = threadIdx.x;
    const int lane = tid & 31, wid = tid >> 5;
    const int g = lane >> 2, tg = lane & 3;
    const int wm = (wid >> 2) * 32;   // 2 warp-rows
    const int wn = (wid & 3) * 64;    // 4 warp-cols

    const int z = blockIdx.x;
    const int b = z >> 7, r = z & 127, wb = r >> 1, half = r & 1;
    const float* qbase = qk + ((size_t)(b * 8192 + wb * 128 + half * 64)) * 1024;
    const float* kbase = qk + (size_t)b * 8192 * 1024 + 512;
    const int kn0 = wb * 128 - 128;

    const int lr = tid >> 3, lc = (tid & 7) * 4;

    // ---- Phase 1: S = Q @ K2^T ----------------------------------------------
    {
        float acc[2][8][4];
#pragma unroll
        for (int mt = 0; mt < 2; mt++)
#pragma unroll
            for (int nt = 0; nt < 8; nt++)
#pragma unroll
                for (int q = 0; q < 4; q++) acc[mt][nt][q] = 0.f;

        float4 rq[2], rk[8];
        auto ld1 = [&](int k0) {
#pragma unroll
            for (int it = 0; it < 2; it++)
                rq[it] = *(const float4*)(qbase + (size_t)(lr + it * 32) * 1024 + k0 + lc);
#pragma unroll
            for (int it = 0; it < 8; it++) {
                int n = kn0 + lr + it * 32;
                rk[it] = make_float4(0.f, 0.f, 0.f, 0.f);
                if (n >= 0)
                    rk[it] = *(const float4*)(kbase + (size_t)n * 1024 + k0 + lc);
            }
        };
        auto st1 = [&](int buf) {
            float* Qd = U + buf * 11520;
            float* Kd = Qd + 64 * 36;
#pragma unroll
            for (int it = 0; it < 2; it++) {
                int base = (lr + it * 32) * 36 + lc;
                Qd[base + 0] = __uint_as_float(f2tf(rq[it].x));
                Qd[base + 1] = __uint_as_float(f2tf(rq[it].y));
                Qd[base + 2] = __uint_as_float(f2tf(rq[it].z));
                Qd[base + 3] = __uint_as_float(f2tf(rq[it].w));
            }
#pragma unroll
            for (int it = 0; it < 8; it++) {
                int base = (lr + it * 32) * 36 + lc;
                Kd[base + 0] = __uint_as_float(f2tf(rk[it].x));
                Kd[base + 1] = __uint_as_float(f2tf(rk[it].y));
                Kd[base + 2] = __uint_as_float(f2tf(rk[it].z));
                Kd[base + 3] = __uint_as_float(f2tf(rk[it].w));
            }
        };
        auto compute1 = [&](int buf) {
            const float* Qc = U + buf * 11520;
            const float* Kc = Qc + 64 * 36;
#pragma unroll
            for (int ks = 0; ks < 4; ks++) {
                const int kk = ks * 8;
                unsigned af[2][4];
#pragma unroll
                for (int mt = 0; mt < 2; mt++) {
                    int r0 = (wm + mt * 16 + g) * 36 + kk + tg;
                    af[mt][0] = __float_as_uint(Qc[r0]);
                    af[mt][1] = __float_as_uint(Qc[r0 + 8 * 36]);
                    af[mt][2] = __float_as_uint(Qc[r0 + 4]);
                    af[mt][3] = __float_as_uint(Qc[r0 + 8 * 36 + 4]);
                }
#pragma unroll
                for (int nt = 0; nt < 8; nt++) {
                    int r0 = (wn + nt * 8 + g) * 36 + kk + tg;
                    unsigned b0 = __float_as_uint(Kc[r0]);
                    unsigned b1 = __float_as_uint(Kc[r0 + 4]);
#pragma unroll
                    for (int mt = 0; mt < 2; mt++)
                        mma8(acc[mt][nt], af[mt][0], af[mt][1], af[mt][2], af[mt][3], b0, b1);
                }
            }
        };

        ld1(0); st1(0); __syncthreads();
        for (int t = 0; t < 16; t++) {
            if (t + 1 < 16) ld1((t + 1) * 32);
            compute1(t & 1);
            if (t + 1 < 16) st1((t + 1) & 1);
            __syncthreads();
        }

        // scale + causal mask + stage to S
        const float scale = 0.044194173824159216f;  // 512^-0.5
#pragma unroll
        for (int mt = 0; mt < 2; mt++) {
#pragma unroll
            for (int nt = 0; nt < 8; nt++) {
                int row0 = wm + mt * 16 + g;
                int col = wn + nt * 8 + tg * 2;
#pragma unroll
                for (int hh = 0; hh < 2; hh++) {
                    int row = row0 + hh * 8;
                    int lim = half * 64 + row + 128;   // mask: col > qi+128
                    float v0 = acc[mt][nt][hh * 2 + 0] * scale;
                    float v1 = acc[mt][nt][hh * 2 + 1] * scale;
                    S[row * 260 + col] = (col > lim) ? -1e30f : v0;
                    S[row * 260 + col + 1] = (col + 1 > lim) ? -1e30f : v1;
                }
            }
        }
    }
    __syncthreads();

    // ---- Softmax (4 threads/row), convert P to tf32 in-place -----------------
    {
        int row = tid >> 2, l4 = tid & 3;
        float m = -1e30f;
        for (int c = l4; c < 256; c += 4) m = fmaxf(m, S[row * 260 + c]);
        m = fmaxf(m, __shfl_xor_sync(0xffffffffu, m, 1));
        m = fmaxf(m, __shfl_xor_sync(0xffffffffu, m, 2));
        float s = 0.f;
        for (int c = l4; c < 256; c += 4) {
            float e = __expf(S[row * 260 + c] - m);
            S[row * 260 + c] = e;
            s += e;
        }
        s += __shfl_xor_sync(0xffffffffu, s, 1);
        s += __shfl_xor_sync(0xffffffffu, s, 2);
        float inv = 1.f / s;
        for (int c = l4; c < 256; c += 4)
            S[row * 260 + c] = __uint_as_float(f2tf(S[row * 260 + c] * inv));
    }
    __syncthreads();

    // ---- Phase 2: O = P @ V (V := K rows; not transposed) ---------------------
    float* outbase = outa + ((size_t)(b * 8192 + wb * 128 + half * 64)) * 512;
    const int vr = tid >> 3;           // 0..31 (j within 32-chunk)
    const int vc = (tid & 7) * 4;      // col base; +u*32

    for (int d0 = 0; d0 < 512; d0 += 256) {
        float acc2[2][8][4];
#pragma unroll
        for (int mt = 0; mt < 2; mt++)
#pragma unroll
            for (int nt = 0; nt < 8; nt++)
#pragma unroll
                for (int q = 0; q < 4; q++) acc2[mt][nt][q] = 0.f;

        float4 rv[8];
        auto ldv = [&](int j0) {
            int n = kn0 + j0 + vr;
#pragma unroll
            for (int u = 0; u < 8; u++) {
                rv[u] = make_float4(0.f, 0.f, 0.f, 0.f);
                if (n >= 0)
                    rv[u] = *(const float4*)(kbase + (size_t)n * 1024 + d0 + vc + u * 32);
            }
        };
        auto stv = [&](int buf) {
            float* Vd = U + buf * 8448;   // pitch 264 (== 8 mod 32)
            int base = vr * 264 + vc;
#pragma unroll
            for (int u = 0; u < 8; u++) {
                Vd[base + u * 32 + 0] = __uint_as_float(f2tf(rv[u].x));
                Vd[base + u * 32 + 1] = __uint_as_float(f2tf(rv[u].y));
                Vd[base + u * 32 + 2] = __uint_as_float(f2tf(rv[u].z));
                Vd[base + u * 32 + 3] = __uint_as_float(f2tf(rv[u].w));
            }
        };
        auto compute2 = [&](int buf, int j0) {
            const float* Vd = U + buf * 8448;
#pragma unroll
            for (int ks = 0; ks < 4; ks++) {
                unsigned af[2][4];
#pragma unroll
                for (int mt = 0; mt < 2; mt++) {
                    int r0 = (wm + mt * 16 + g) * 260 + j0 + ks * 8 + tg;
                    af[mt][0] = __float_as_uint(S[r0]);
                    af[mt][1] = __float_as_uint(S[r0 + 8 * 260]);
                    af[mt][2] = __float_as_uint(S[r0 + 4]);
                    af[mt][3] = __float_as_uint(S[r0 + 8 * 260 + 4]);
                }
#pragma unroll
                for (int nt = 0; nt < 8; nt++) {
                    int col = wn + nt * 8 + g;
                    unsigned b0 = __float_as_uint(Vd[(ks * 8 + tg) * 264 + col]);
                    unsigned b1 = __float_as_uint(Vd[(ks * 8 + tg + 4) * 264 + col]);
#pragma unroll
                    for (int mt = 0; mt < 2; mt++)
                        mma8(acc2[mt][nt], af[mt][0], af[mt][1], af[mt][2], af[mt][3], b0, b1);
                }
            }
        };

        ldv(0); stv(0); __syncthreads();
        for (int t = 0; t < 8; t++) {
            if (t + 1 < 8) ldv((t + 1) * 32);
            compute2(t & 1, t * 32);
            if (t + 1 < 8) stv((t + 1) & 1);
            __syncthreads();
        }

#pragma unroll
        for (int mt = 0; mt < 2; mt++) {
            int row = wm + mt * 16 + g;
#pragma unroll
            for (int nt = 0; nt < 8; nt++) {
                int col = d0 + wn + nt * 8 + tg * 2;
                *(float2*)(outbase + (size_t)row * 512 + col) =
                    make_float2(acc2[mt][nt][0], acc2[mt][nt][1]);
                *(float2*)(outbase + (size_t)(row + 8) * 512 + col) =
                    make_float2(acc2[mt][nt][2], acc2[mt][nt][3]);
            }
        }
    }
}

// ---------------------------------------------------------------------------
extern "C" void kernel_launch(void* const* d_in, const int* in_sizes, int n_in,
                              void* d_out, int out_size)
{
    const float* x     = (const float*)d_in[0];   // (4, 8192, 512)
    const float* w_qkv = (const float*)d_in[1];   // (1536, 512) — V rows dead (ref bug)
    const float* w_out = (const float*)d_in[2];   // (512, 512)
    const float* b_out = (const float*)d_in[3];   // (512,)
    float* out = (float*)d_out;

    float* qkbuf = nullptr;
    float* attbuf = nullptr;
    cudaGetSymbolAddress((void**)&qkbuf, g_qk);
    cudaGetSymbolAddress((void**)&attbuf, g_att);

    const int gemm_smem = 2 * (128 * 36 + 128 * 36) * 4;                 // 73728 B
    const int attn_smem = (64 * 260 + 2 * 11520) * 4;                    // 158720 B
    cudaFuncSetAttribute(gemm_tf32, cudaFuncAttributeMaxDynamicSharedMemorySize, gemm_smem);
    cudaFuncSetAttribute(attn_tf32, cudaFuncAttributeMaxDynamicSharedMemorySize, attn_smem);

    // 1) Q,K projection: [32768,512] @ [1024,512]^T -> g_qk
    dim3 g1(1024 / 128, MTOT / 128);
    gemm_tf32<<<g1, 256, gemm_smem>>>(x, w_qkv, nullptr, qkbuf, MTOT, 1024, 512);

    // 2) Windowed attention (V := K per reference bug) -> g_att
    attn_tf32<<<512, 256, attn_smem>>>(qkbuf, attbuf);

    // 3) Output projection + bias: [32768,512] @ [512,512]^T -> out
    dim3 g3(512 / 128, MTOT / 128);
    gemm_tf32<<<g3, 256, gemm_smem>>>(attbuf, w_out, b_out, out, MTOT, 512, 512);
}

// round 7
// speedup vs baseline: 3.7373x; 1.2480x over previous
#include <cuda_runtime.h>
#include <cuda_fp16.h>
#include <cstdint>
#include <cstddef>

// B=4, N=8192, DIN=512, DINNER=512, DOUT=512, W=128 -> 64 windows/batch, pad=0
#define MTOT 32768

// Scratch (alloc-guard-safe __device__ globals)
__device__ float g_qk[(size_t)MTOT * 1024];   // [m][0:512]=Q, [m][512:1024]=K
__device__ float g_att[(size_t)MTOT * 512];   // attention output

__device__ __forceinline__ uint32_t h2(float a, float b) {
    __half2 h = __floats2half2_rn(a, b);
    return *(uint32_t*)&h;
}
// fp16 mma m16n8k16, fp32 accumulate
__device__ __forceinline__ void mma16(float* c, uint32_t a0, uint32_t a1, uint32_t a2, uint32_t a3,
                                      uint32_t b0, uint32_t b1) {
    asm volatile("mma.sync.aligned.m16n8k16.row.col.f32.f16.f16.f32 "
                 "{%0,%1,%2,%3}, {%4,%5,%6,%7}, {%8,%9}, {%0,%1,%2,%3};"
                 : "+f"(c[0]), "+f"(c[1]), "+f"(c[2]), "+f"(c[3])
                 : "r"(a0), "r"(a1), "r"(a2), "r"(a3), "r"(b0), "r"(b1));
}

// ---------------------------------------------------------------------------
// C[M,Nc] = A[M,K] @ B[Nc,K]^T (+bias). fp16 mma, 128x128x32 tiles, dbl-buffered
// SMEM (half, pitch 40 -> conflict-free frags). 8 warps = 4(m) x 2(n), 32x64 warp tile.
// ---------------------------------------------------------------------------
#define GP 40                       // half pitch per SMEM row
#define GSTG (128 * GP * 2 * 2)     // bytes per stage (A tile + B tile) = 20480

__global__ __launch_bounds__(256, 2)
void gemm_f16(const float* __restrict__ A, const float* __restrict__ Bm,
              const float* __restrict__ bias, float* __restrict__ C,
              int M, int Nc, int K)
{
    extern __shared__ char shb[];

    const int tid = threadIdx.x;
    const int lane = tid & 31, wid = tid >> 5;
    const int g = lane >> 2, tg = lane & 3;
    const int wm = (wid >> 1) * 32;
    const int wn = (wid & 1) * 64;
    const float* Ab = A + (size_t)blockIdx.y * 128 * K;
    const float* Bb = Bm + (size_t)blockIdx.x * 128 * K;
    const int lr = tid >> 3, lc = (tid & 7) * 4;

    float acc[2][8][4];
#pragma unroll
    for (int mt = 0; mt < 2; mt++)
#pragma unroll
        for (int nt = 0; nt < 8; nt++)
#pragma unroll
            for (int q = 0; q < 4; q++) acc[mt][nt][q] = 0.f;

    uint32_t ha[4][2], hb[4][2];
    auto ldg = [&](int k0) {
#pragma unroll
        for (int it = 0; it < 4; it++) {
            float4 va = *(const float4*)(Ab + (size_t)(lr + it * 32) * K + k0 + lc);
            float4 vb = *(const float4*)(Bb + (size_t)(lr + it * 32) * K + k0 + lc);
            ha[it][0] = h2(va.x, va.y); ha[it][1] = h2(va.z, va.w);
            hb[it][0] = h2(vb.x, vb.y); hb[it][1] = h2(vb.z, vb.w);
        }
    };
    auto sts = [&](int buf) {
        uint32_t* Ad = (uint32_t*)(shb + buf * GSTG);
        uint32_t* Bd = Ad + 128 * (GP / 2);
#pragma unroll
        for (int it = 0; it < 4; it++) {
            int base = (lr + it * 32) * (GP / 2) + (tid & 7) * 2;
            *(uint2*)(Ad + base) = make_uint2(ha[it][0], ha[it][1]);
            *(uint2*)(Bd + base) = make_uint2(hb[it][0], hb[it][1]);
        }
    };
    auto compute = [&](int buf) {
        const uint32_t* Ac = (const uint32_t*)(shb + buf * GSTG);
        const uint32_t* Bc = Ac + 128 * (GP / 2);
#pragma unroll
        for (int ks = 0; ks < 2; ks++) {
            const int kw = ks * 8 + tg;          // uint index of (kk + 2tg)
            uint32_t af[2][4];
#pragma unroll
            for (int mt = 0; mt < 2; mt++) {
                int r0 = (wm + mt * 16 + g) * (GP / 2) + kw;
                af[mt][0] = Ac[r0];
                af[mt][1] = Ac[r0 + 8 * (GP / 2)];
                af[mt][2] = Ac[r0 + 4];
                af[mt][3] = Ac[r0 + 8 * (GP / 2) + 4];
            }
#pragma unroll
            for (int nt = 0; nt < 8; nt++) {
                int r0 = (wn + nt * 8 + g) * (GP / 2) + kw;
                uint32_t b0 = Bc[r0];
                uint32_t b1 = Bc[r0 + 4];
#pragma unroll
                for (int mt = 0; mt < 2; mt++)
                    mma16(acc[mt][nt], af[mt][0], af[mt][1], af[mt][2], af[mt][3], b0, b1);
            }
        }
    };

    ldg(0); sts(0); __syncthreads();
    const int T = K / 32;
    for (int t = 0; t < T; t++) {
        if (t + 1 < T) ldg((t + 1) * 32);
        compute(t & 1);
        if (t + 1 < T) sts((t + 1) & 1);
        __syncthreads();
    }

#pragma unroll
    for (int mt = 0; mt < 2; mt++) {
        int row = blockIdx.y * 128 + wm + mt * 16 + g;
#pragma unroll
        for (int nt = 0; nt < 8; nt++) {
            int col = blockIdx.x * 128 + wn + nt * 8 + tg * 2;
            float b0 = 0.f, b1 = 0.f;
            if (bias) { b0 = bias[col]; b1 = bias[col + 1]; }
            *(float2*)(C + (size_t)row * Nc + col) =
                make_float2(acc[mt][nt][0] + b0, acc[mt][nt][1] + b1);
            *(float2*)(C + (size_t)(row + 8) * Nc + col) =
                make_float2(acc[mt][nt][2] + b0, acc[mt][nt][3] + b1);
        }
    }
}

// ---------------------------------------------------------------------------
// Windowed attention (fp16 mma). 512 blocks: b * 64 windows * 2 half-windows.
// 64 queries x 256 keys; causal mask col <= qi+128; softmax fp32;
// O = P @ K2 (reference bug: V := K). P/V kept fp32 in SMEM, RN->fp16 at frag load.
// ---------------------------------------------------------------------------
#define A1STG (64 * GP + 256 * GP)      // halves per phase-1 stage (Q + K)
__global__ __launch_bounds__(256)
void attn_f16(const float* __restrict__ qk, float* __restrict__ outa)
{
    extern __shared__ float sh[];
    float* S = sh;                                   // 64 x 260 fp32
    char*  Ub = (char*)(sh + 64 * 260);              // phase1: half Q/K dbl-buf; phase2: fp32 V dbl-buf
    float* Uf = sh + 64 * 260;

    const int tid = threadIdx.x;
    const int lane = tid & 31, wid = tid >> 5;
    const int g = lane >> 2, tg = lane & 3;
    const int wm = (wid >> 2) * 32;
    const int wn = (wid & 3) * 64;

    const int z = blockIdx.x;
    const int b = z >> 7, r = z & 127, wb = r >> 1, half = r & 1;
    const float* qbase = qk + ((size_t)(b * 8192 + wb * 128 + half * 64)) * 1024;
    const float* kbase = qk + (size_t)b * 8192 * 1024 + 512;
    const int kn0 = wb * 128 - 128;

    const int lr = tid >> 3;

    // ---- Phase 1: S = Q @ K2^T
    {
        float acc[2][8][4];
#pragma unroll
        for (int mt = 0; mt < 2; mt++)
#pragma unroll
            for (int nt = 0; nt < 8; nt++)
#pragma unroll
                for (int q = 0; q < 4; q++) acc[mt][nt][q] = 0.f;

        const int lc = (tid & 7) * 4;
        uint32_t hq[2][2], hk[8][2];
        auto ld1 = [&](int k0) {
#pragma unroll
            for (int it = 0; it < 2; it++) {
                float4 v = *(const float4*)(qbase + (size_t)(lr + it * 32) * 1024 + k0 + lc);
                hq[it][0] = h2(v.x, v.y); hq[it][1] = h2(v.z, v.w);
            }
#pragma unroll
            for (int it = 0; it < 8; it++) {
                int n = kn0 + lr + it * 32;
                float4 v = make_float4(0.f, 0.f, 0.f, 0.f);
                if (n >= 0)
                    v = *(const float4*)(kbase + (size_t)n * 1024 + k0 + lc);
                hk[it][0] = h2(v.x, v.y); hk[it][1] = h2(v.z, v.w);
            }
        };
        auto st1 = [&](int buf) {
            uint32_t* Qd = (uint32_t*)(Ub + buf * A1STG * 2);
            uint32_t* Kd = Qd + 64 * (GP / 2);
#pragma unroll
            for (int it = 0; it < 2; it++) {
                int base = (lr + it * 32) * (GP / 2) + (tid & 7) * 2;
                *(uint2*)(Qd + base) = make_uint2(hq[it][0], hq[it][1]);
            }
#pragma unroll
            for (int it = 0; it < 8; it++) {
                int base = (lr + it * 32) * (GP / 2) + (tid & 7) * 2;
                *(uint2*)(Kd + base) = make_uint2(hk[it][0], hk[it][1]);
            }
        };
        auto compute1 = [&](int buf) {
            const uint32_t* Qc = (const uint32_t*)(Ub + buf * A1STG * 2);
            const uint32_t* Kc = Qc + 64 * (GP / 2);
#pragma unroll
            for (int ks = 0; ks < 2; ks++) {
                const int kw = ks * 8 + tg;
                uint32_t af[2][4];
#pragma unroll
                for (int mt = 0; mt < 2; mt++) {
                    int r0 = (wm + mt * 16 + g) * (GP / 2) + kw;
                    af[mt][0] = Qc[r0];
                    af[mt][1] = Qc[r0 + 8 * (GP / 2)];
                    af[mt][2] = Qc[r0 + 4];
                    af[mt][3] = Qc[r0 + 8 * (GP / 2) + 4];
                }
#pragma unroll
                for (int nt = 0; nt < 8; nt++) {
                    int r0 = (wn + nt * 8 + g) * (GP / 2) + kw;
                    uint32_t b0 = Kc[r0];
                    uint32_t b1 = Kc[r0 + 4];
#pragma unroll
                    for (int mt = 0; mt < 2; mt++)
                        mma16(acc[mt][nt], af[mt][0], af[mt][1], af[mt][2], af[mt][3], b0, b1);
                }
            }
        };

        ld1(0); st1(0); __syncthreads();
        for (int t = 0; t < 16; t++) {
            if (t + 1 < 16) ld1((t + 1) * 32);
            compute1(t & 1);
            if (t + 1 < 16) st1((t + 1) & 1);
            __syncthreads();
        }

        const float scale = 0.044194173824159216f;  // 512^-0.5
#pragma unroll
        for (int mt = 0; mt < 2; mt++) {
#pragma unroll
            for (int nt = 0; nt < 8; nt++) {
                int row0 = wm + mt * 16 + g;
                int col = wn + nt * 8 + tg * 2;
#pragma unroll
                for (int hh = 0; hh < 2; hh++) {
                    int row = row0 + hh * 8;
                    int lim = half * 64 + row + 128;
                    float v0 = acc[mt][nt][hh * 2 + 0] * scale;
                    float v1 = acc[mt][nt][hh * 2 + 1] * scale;
                    S[row * 260 + col] = (col > lim) ? -1e30f : v0;
                    S[row * 260 + col + 1] = (col + 1 > lim) ? -1e30f : v1;
                }
            }
        }
    }
    __syncthreads();

    // ---- Softmax (fp32; P stays fp32 in S)
    {
        int row = tid >> 2, l4 = tid & 3;
        float m = -1e30f;
        for (int c = l4; c < 256; c += 4) m = fmaxf(m, S[row * 260 + c]);
        m = fmaxf(m, __shfl_xor_sync(0xffffffffu, m, 1));
        m = fmaxf(m, __shfl_xor_sync(0xffffffffu, m, 2));
        float s = 0.f;
        for (int c = l4; c < 256; c += 4) {
            float e = __expf(S[row * 260 + c] - m);
            S[row * 260 + c] = e;
            s += e;
        }
        s += __shfl_xor_sync(0xffffffffu, s, 1);
        s += __shfl_xor_sync(0xffffffffu, s, 2);
        float inv = 1.f / s;
        for (int c = l4; c < 256; c += 4) S[row * 260 + c] *= inv;
    }
    __syncthreads();

    // ---- Phase 2: O = P @ V  (V := K rows, reference bug). V fp32 in SMEM.
    float* outbase = outa + ((size_t)(b * 8192 + wb * 128 + half * 64)) * 512;
    const int vr = tid >> 3;
    const int vc = (tid & 7) * 4;

    for (int d0 = 0; d0 < 512; d0 += 256) {
        float acc2[2][8][4];
#pragma unroll
        for (int mt = 0; mt < 2; mt++)
#pragma unroll
            for (int nt = 0; nt < 8; nt++)
#pragma unroll
                for (int q = 0; q < 4; q++) acc2[mt][nt][q] = 0.f;

        float4 rv[8];
        auto ldv = [&](int j0) {
            int n = kn0 + j0 + vr;
#pragma unroll
            for (int u = 0; u < 8; u++) {
                rv[u] = make_float4(0.f, 0.f, 0.f, 0.f);
                if (n >= 0)
                    rv[u] = *(const float4*)(kbase + (size_t)n * 1024 + d0 + vc + u * 32);
            }
        };
        auto stv = [&](int buf) {
            float* Vd = Uf + buf * 8448;   // pitch 264 fp32 (j rows, d cols)
            int base = vr * 264 + vc;
#pragma unroll
            for (int u = 0; u < 8; u++)
                *(float4*)(Vd + base + u * 32) = rv[u];
        };
        auto compute2 = [&](int buf, int j0) {
            const float* Vd = Uf + buf * 8448;
#pragma unroll
            for (int ks = 0; ks < 2; ks++) {
                const int kk = ks * 16;
                uint32_t af[2][4];
#pragma unroll
                for (int mt = 0; mt < 2; mt++) {
                    int r0 = (wm + mt * 16 + g) * 260 + j0 + kk + tg * 2;
                    float2 p0 = *(const float2*)(S + r0);
                    float2 p1 = *(const float2*)(S + r0 + 8 * 260);
                    float2 p2 = *(const float2*)(S + r0 + 8);
                    float2 p3 = *(const float2*)(S + r0 + 8 * 260 + 8);
                    af[mt][0] = h2(p0.x, p0.y);
                    af[mt][1] = h2(p1.x, p1.y);
                    af[mt][2] = h2(p2.x, p2.y);
                    af[mt][3] = h2(p3.x, p3.y);
                }
#pragma unroll
                for (int nt = 0; nt < 8; nt++) {
                    int col = wn + nt * 8 + g;
                    int jr = kk + tg * 2;
                    uint32_t b0 = h2(Vd[jr * 264 + col],       Vd[(jr + 1) * 264 + col]);
                    uint32_t b1 = h2(Vd[(jr + 8) * 264 + col], Vd[(jr + 9) * 264 + col]);
#pragma unroll
                    for (int mt = 0; mt < 2; mt++)
                        mma16(acc2[mt][nt], af[mt][0], af[mt][1], af[mt][2], af[mt][3], b0, b1);
                }
            }
        };

        ldv(0); stv(0); __syncthreads();
        for (int t = 0; t < 8; t++) {
            if (t + 1 < 8) ldv((t + 1) * 32);
            compute2(t & 1, t * 32);
            if (t + 1 < 8) stv((t + 1) & 1);
            __syncthreads();
        }

#pragma unroll
        for (int mt = 0; mt < 2; mt++) {
            int row = wm + mt * 16 + g;
#pragma unroll
            for (int nt = 0; nt < 8; nt++) {
                int col = d0 + wn + nt * 8 + tg * 2;
                *(float2*)(outbase + (size_t)row * 512 + col) =
                    make_float2(acc2[mt][nt][0], acc2[mt][nt][1]);
                *(float2*)(outbase + (size_t)(row + 8) * 512 + col) =
                    make_float2(acc2[mt][nt][2], acc2[mt][nt][3]);
            }
        }
    }
}

// ---------------------------------------------------------------------------
extern "C" void kernel_launch(void* const* d_in, const int* in_sizes, int n_in,
                              void* d_out, int out_size)
{
    const float* x     = (const float*)d_in[0];   // (4, 8192, 512)
    const float* w_qkv = (const float*)d_in[1];   // (1536, 512) — V rows dead (ref bug)
    const float* w_out = (const float*)d_in[2];   // (512, 512)
    const float* b_out = (const float*)d_in[3];   // (512,)
    float* out = (float*)d_out;

    float* qkbuf = nullptr;
    float* attbuf = nullptr;
    cudaGetSymbolAddress((void**)&qkbuf, g_qk);
    cudaGetSymbolAddress((void**)&attbuf, g_att);

    const int gemm_smem = 2 * GSTG;                                    // 40960 B
    const int p1 = 2 * A1STG * 2;                                      // 51200 B (half Q/K)
    const int p2 = 2 * 8448 * 4;                                       // 67584 B (fp32 V)
    const int attn_smem = 64 * 260 * 4 + (p1 > p2 ? p1 : p2);          // 134144 B
    cudaFuncSetAttribute(gemm_f16, cudaFuncAttributeMaxDynamicSharedMemorySize, gemm_smem);
    cudaFuncSetAttribute(attn_f16, cudaFuncAttributeMaxDynamicSharedMemorySize, attn_smem);

    // 1) Q,K projection: [32768,512] @ [1024,512]^T -> g_qk
    dim3 g1(1024 / 128, MTOT / 128);
    gemm_f16<<<g1, 256, gemm_smem>>>(x, w_qkv, nullptr, qkbuf, MTOT, 1024, 512);

    // 2) Windowed attention (V := K per reference bug) -> g_att
    attn_f16<<<512, 256, attn_smem>>>(qkbuf, attbuf);

    // 3) Output projection + bias: [32768,512] @ [512,512]^T -> out
    dim3 g3(512 / 128, MTOT / 128);
    gemm_f16<<<g3, 256, gemm_smem>>>(attbuf, w_out, b_out, out, MTOT, 512, 512);
}

// round 8
// speedup vs baseline: 4.5560x; 1.2190x over previous
#include <cuda_runtime.h>
#include <cuda_fp16.h>
#include <cstdint>
#include <cstddef>

// B=4, N=8192, DIN=512, DINNER=512, DOUT=512, W=128 -> 64 windows/batch, pad=0
#define MTOT 32768

// Scratch (alloc-guard-safe __device__ globals), fp16
__device__ __half g_qk[(size_t)MTOT * 1024];   // [m][0:512]=Q, [m][512:1024]=K
__device__ __half g_att[(size_t)MTOT * 512];   // attention output

__device__ __forceinline__ uint32_t h2(float a, float b) {
    __half2 h = __floats2half2_rn(a, b);
    return *(uint32_t*)&h;
}
__device__ __forceinline__ uint32_t smem_u32(const void* p) {
    uint32_t a;
    asm("{ .reg .u64 t; cvta.to.shared.u64 t, %1; cvt.u32.u64 %0, t; }" : "=r"(a) : "l"(p));
    return a;
}
// fp16 mma m16n8k16, fp32 accumulate
__device__ __forceinline__ void mma16(float* c, uint32_t a0, uint32_t a1, uint32_t a2, uint32_t a3,
                                      uint32_t b0, uint32_t b1) {
    asm volatile("mma.sync.aligned.m16n8k16.row.col.f32.f16.f16.f32 "
                 "{%0,%1,%2,%3}, {%4,%5,%6,%7}, {%8,%9}, {%0,%1,%2,%3};"
                 : "+f"(c[0]), "+f"(c[1]), "+f"(c[2]), "+f"(c[3])
                 : "r"(a0), "r"(a1), "r"(a2), "r"(a3), "r"(b0), "r"(b1));
}
__device__ __forceinline__ void ldsm4(uint32_t* r, uint32_t addr) {
    asm volatile("ldmatrix.sync.aligned.m8n8.x4.shared.b16 {%0,%1,%2,%3}, [%4];"
                 : "=r"(r[0]), "=r"(r[1]), "=r"(r[2]), "=r"(r[3]) : "r"(addr));
}

// ---------------------------------------------------------------------------
// GEMM: C[M,Nc] = A[M,K] @ B[Nc,K]^T (+bias). fp16 mma + ldmatrix fragments.
// 128x128x32 tiles dbl-buffered, SMEM half pitch 40 (80B rows).
// 8 warps = 4(m) x 2(n); warp tile 32x64. A may be half (AHALF), C may be half (OHALF).
// ---------------------------------------------------------------------------
#define GP 40                       // halves per SMEM row
#define GROWB 80                    // bytes per SMEM row
#define GSTG (128 * GROWB * 2)      // bytes per stage (A tile + B tile) = 20480

template<bool AHALF, bool OHALF>
__global__ __launch_bounds__(256, 2)
void gemm_f16(const void* __restrict__ Ap, const float* __restrict__ Bm,
              const float* __restrict__ bias, void* __restrict__ Cp,
              int M, int Nc, int K)
{
    extern __shared__ char shb[];
    const uint32_t sb = smem_u32(shb);

    const int tid = threadIdx.x;
    const int lane = tid & 31, wid = tid >> 5;
    const int g = lane >> 2, tg = lane & 3;
    const int wm = (wid >> 1) * 32;
    const int wn = (wid & 1) * 64;
    const int lr = tid >> 3, lc = (tid & 7) * 4;

    // ldmatrix per-lane addresses (byte offsets into a stage)
    uint32_t aaddr[2], baddr[4];
#pragma unroll
    for (int mt = 0; mt < 2; mt++) {
        int row = wm + mt * 16 + (lane & 7) + ((lane >> 3) & 1) * 8;
        aaddr[mt] = sb + row * GROWB + (lane >> 4) * 16;
    }
#pragma unroll
    for (int ntp = 0; ntp < 4; ntp++) {
        int row = wn + ntp * 16 + (lane & 7) + (lane >> 4) * 8;
        baddr[ntp] = sb + 128 * GROWB + row * GROWB + ((lane >> 3) & 1) * 16;
    }

    const float* Bb = Bm + (size_t)blockIdx.x * 128 * K;

    float acc[2][8][4];
#pragma unroll
    for (int mt = 0; mt < 2; mt++)
#pragma unroll
        for (int nt = 0; nt < 8; nt++)
#pragma unroll
            for (int q = 0; q < 4; q++) acc[mt][nt][q] = 0.f;

    uint32_t ha[4][2], hb[4][2];
    auto ldg = [&](int k0) {
        if (AHALF) {
            const __half* Ab = (const __half*)Ap + (size_t)blockIdx.y * 128 * K;
#pragma unroll
            for (int it = 0; it < 4; it++) {
                uint2 v = *(const uint2*)(Ab + (size_t)(lr + it * 32) * K + k0 + lc);
                ha[it][0] = v.x; ha[it][1] = v.y;
            }
        } else {
            const float* Ab = (const float*)Ap + (size_t)blockIdx.y * 128 * K;
#pragma unroll
            for (int it = 0; it < 4; it++) {
                float4 v = *(const float4*)(Ab + (size_t)(lr + it * 32) * K + k0 + lc);
                ha[it][0] = h2(v.x, v.y); ha[it][1] = h2(v.z, v.w);
            }
        }
#pragma unroll
        for (int it = 0; it < 4; it++) {
            float4 v = *(const float4*)(Bb + (size_t)(lr + it * 32) * K + k0 + lc);
            hb[it][0] = h2(v.x, v.y); hb[it][1] = h2(v.z, v.w);
        }
    };
    auto sts = [&](int buf) {
        uint32_t* Ad = (uint32_t*)(shb + buf * GSTG);
        uint32_t* Bd = Ad + 128 * (GP / 2);
#pragma unroll
        for (int it = 0; it < 4; it++) {
            int base = (lr + it * 32) * (GP / 2) + (tid & 7) * 2;
            *(uint2*)(Ad + base) = make_uint2(ha[it][0], ha[it][1]);
            *(uint2*)(Bd + base) = make_uint2(hb[it][0], hb[it][1]);
        }
    };
    auto compute = [&](int buf) {
        const uint32_t so = buf * GSTG;
#pragma unroll
        for (int ks = 0; ks < 2; ks++) {
            uint32_t af[2][4];
            ldsm4(af[0], aaddr[0] + so + ks * 32);
            ldsm4(af[1], aaddr[1] + so + ks * 32);
#pragma unroll
            for (int ntp = 0; ntp < 4; ntp++) {
                uint32_t bf[4];
                ldsm4(bf, baddr[ntp] + so + ks * 32);
#pragma unroll
                for (int mt = 0; mt < 2; mt++) {
                    mma16(acc[mt][ntp * 2],     af[mt][0], af[mt][1], af[mt][2], af[mt][3], bf[0], bf[1]);
                    mma16(acc[mt][ntp * 2 + 1], af[mt][0], af[mt][1], af[mt][2], af[mt][3], bf[2], bf[3]);
                }
            }
        }
    };

    ldg(0); sts(0); __syncthreads();
    const int T = K / 32;
    for (int t = 0; t < T; t++) {
        if (t + 1 < T) ldg((t + 1) * 32);
        compute(t & 1);
        if (t + 1 < T) sts((t + 1) & 1);
        __syncthreads();
    }

#pragma unroll
    for (int mt = 0; mt < 2; mt++) {
        int row = blockIdx.y * 128 + wm + mt * 16 + g;
#pragma unroll
        for (int nt = 0; nt < 8; nt++) {
            int col = blockIdx.x * 128 + wn + nt * 8 + tg * 2;
            float b0 = 0.f, b1 = 0.f;
            if (bias) { b0 = bias[col]; b1 = bias[col + 1]; }
            if (OHALF) {
                __half* C = (__half*)Cp;
                *(uint32_t*)(C + (size_t)row * Nc + col) =
                    h2(acc[mt][nt][0] + b0, acc[mt][nt][1] + b1);
                *(uint32_t*)(C + (size_t)(row + 8) * Nc + col) =
                    h2(acc[mt][nt][2] + b0, acc[mt][nt][3] + b1);
            } else {
                float* C = (float*)Cp;
                *(float2*)(C + (size_t)row * Nc + col) =
                    make_float2(acc[mt][nt][0] + b0, acc[mt][nt][1] + b1);
                *(float2*)(C + (size_t)(row + 8) * Nc + col) =
                    make_float2(acc[mt][nt][2] + b0, acc[mt][nt][3] + b1);
            }
        }
    }
}

// ---------------------------------------------------------------------------
// Windowed attention. 512 blocks: b * 64 windows * 2 half-windows.
// Q,K read as fp16 from g_qk (no conversion). Phase1 via ldmatrix fragments.
// Softmax fp32. O = P @ K2 (reference bug: V := K), output fp16 into g_att.
// ---------------------------------------------------------------------------
#define A1B (64 * GROWB + 256 * GROWB)    // bytes per phase-1 stage (Q + K) = 25600

__global__ __launch_bounds__(256)
void attn_f16(const __half* __restrict__ qk, __half* __restrict__ outa)
{
    extern __shared__ float sh[];
    float* S = sh;                                   // 64 x 260 fp32
    char*  Ub = (char*)(sh + 64 * 260);              // ph1: half Q/K dbl-buf; ph2: fp32 V dbl-buf
    float* Uf = sh + 64 * 260;
    const uint32_t sbU = smem_u32(Ub);

    const int tid = threadIdx.x;
    const int lane = tid & 31, wid = tid >> 5;
    const int g = lane >> 2, tg = lane & 3;
    const int wm = (wid >> 2) * 32;
    const int wn = (wid & 3) * 64;

    const int z = blockIdx.x;
    const int b = z >> 7, r = z & 127, wb = r >> 1, half = r & 1;
    const __half* qbase = qk + ((size_t)(b * 8192 + wb * 128 + half * 64)) * 1024;
    const __half* kbase = qk + (size_t)b * 8192 * 1024 + 512;
    const int kn0 = wb * 128 - 128;

    const int lr = tid >> 3, lc = (tid & 7) * 4;

    // ---- Phase 1: S = Q @ K2^T (ldmatrix fragments)
    {
        uint32_t aaddr[2], baddr[4];
#pragma unroll
        for (int mt = 0; mt < 2; mt++) {
            int row = wm + mt * 16 + (lane & 7) + ((lane >> 3) & 1) * 8;
            aaddr[mt] = sbU + row * GROWB + (lane >> 4) * 16;
        }
#pragma unroll
        for (int ntp = 0; ntp < 4; ntp++) {
            int row = wn + ntp * 16 + (lane & 7) + (lane >> 4) * 8;
            baddr[ntp] = sbU + 64 * GROWB + row * GROWB + ((lane >> 3) & 1) * 16;
        }

        float acc[2][8][4];
#pragma unroll
        for (int mt = 0; mt < 2; mt++)
#pragma unroll
            for (int nt = 0; nt < 8; nt++)
#pragma unroll
                for (int q = 0; q < 4; q++) acc[mt][nt][q] = 0.f;

        uint2 hq[2], hk[8];
        auto ld1 = [&](int k0) {
#pragma unroll
            for (int it = 0; it < 2; it++)
                hq[it] = *(const uint2*)(qbase + (size_t)(lr + it * 32) * 1024 + k0 + lc);
#pragma unroll
            for (int it = 0; it < 8; it++) {
                int n = kn0 + lr + it * 32;
                hk[it] = make_uint2(0u, 0u);
                if (n >= 0)
                    hk[it] = *(const uint2*)(kbase + (size_t)n * 1024 + k0 + lc);
            }
        };
        auto st1 = [&](int buf) {
            uint32_t* Qd = (uint32_t*)(Ub + buf * A1B);
            uint32_t* Kd = Qd + 64 * (GP / 2);
#pragma unroll
            for (int it = 0; it < 2; it++)
                *(uint2*)(Qd + (lr + it * 32) * (GP / 2) + (tid & 7) * 2) = hq[it];
#pragma unroll
            for (int it = 0; it < 8; it++)
                *(uint2*)(Kd + (lr + it * 32) * (GP / 2) + (tid & 7) * 2) = hk[it];
        };
        auto compute1 = [&](int buf) {
            const uint32_t so = buf * A1B;
#pragma unroll
            for (int ks = 0; ks < 2; ks++) {
                uint32_t af[2][4];
                ldsm4(af[0], aaddr[0] + so + ks * 32);
                ldsm4(af[1], aaddr[1] + so + ks * 32);
#pragma unroll
                for (int ntp = 0; ntp < 4; ntp++) {
                    uint32_t bf[4];
                    ldsm4(bf, baddr[ntp] + so + ks * 32);
#pragma unroll
                    for (int mt = 0; mt < 2; mt++) {
                        mma16(acc[mt][ntp * 2],     af[mt][0], af[mt][1], af[mt][2], af[mt][3], bf[0], bf[1]);
                        mma16(acc[mt][ntp * 2 + 1], af[mt][0], af[mt][1], af[mt][2], af[mt][3], bf[2], bf[3]);
                    }
                }
            }
        };

        ld1(0); st1(0); __syncthreads();
        for (int t = 0; t < 16; t++) {
            if (t + 1 < 16) ld1((t + 1) * 32);
            compute1(t & 1);
            if (t + 1 < 16) st1((t + 1) & 1);
            __syncthreads();
        }

        const float scale = 0.044194173824159216f;  // 512^-0.5
#pragma unroll
        for (int mt = 0; mt < 2; mt++) {
#pragma unroll
            for (int nt = 0; nt < 8; nt++) {
                int row0 = wm + mt * 16 + g;
                int col = wn + nt * 8 + tg * 2;
#pragma unroll
                for (int hh = 0; hh < 2; hh++) {
                    int row = row0 + hh * 8;
                    int lim = half * 64 + row + 128;
                    float v0 = acc[mt][nt][hh * 2 + 0] * scale;
                    float v1 = acc[mt][nt][hh * 2 + 1] * scale;
                    S[row * 260 + col] = (col > lim) ? -1e30f : v0;
                    S[row * 260 + col + 1] = (col + 1 > lim) ? -1e30f : v1;
                }
            }
        }
    }
    __syncthreads();

    // ---- Softmax (fp32; P stays fp32 in S)
    {
        int row = tid >> 2, l4 = tid & 3;
        float m = -1e30f;
        for (int c = l4; c < 256; c += 4) m = fmaxf(m, S[row * 260 + c]);
        m = fmaxf(m, __shfl_xor_sync(0xffffffffu, m, 1));
        m = fmaxf(m, __shfl_xor_sync(0xffffffffu, m, 2));
        float s = 0.f;
        for (int c = l4; c < 256; c += 4) {
            float e = __expf(S[row * 260 + c] - m);
            S[row * 260 + c] = e;
            s += e;
        }
        s += __shfl_xor_sync(0xffffffffu, s, 1);
        s += __shfl_xor_sync(0xffffffffu, s, 2);
        float inv = 1.f / s;
        for (int c = l4; c < 256; c += 4) S[row * 260 + c] *= inv;
    }
    __syncthreads();

    // ---- Phase 2: O = P @ V  (V := K rows, reference bug). V fp32 in SMEM.
    __half* outbase = outa + ((size_t)(b * 8192 + wb * 128 + half * 64)) * 512;
    const int vr = tid >> 3;
    const int vc = (tid & 7) * 4;

    for (int d0 = 0; d0 < 512; d0 += 256) {
        float acc2[2][8][4];
#pragma unroll
        for (int mt = 0; mt < 2; mt++)
#pragma unroll
            for (int nt = 0; nt < 8; nt++)
#pragma unroll
                for (int q = 0; q < 4; q++) acc2[mt][nt][q] = 0.f;

        uint2 rvh[8];
        auto ldv = [&](int j0) {
            int n = kn0 + j0 + vr;
#pragma unroll
            for (int u = 0; u < 8; u++) {
                rvh[u] = make_uint2(0u, 0u);
                if (n >= 0)
                    rvh[u] = *(const uint2*)(kbase + (size_t)n * 1024 + d0 + vc + u * 32);
            }
        };
        auto stv = [&](int buf) {
            float* Vd = Uf + buf * 8448;   // pitch 264 fp32 (j rows, d cols)
            int base = vr * 264 + vc;
#pragma unroll
            for (int u = 0; u < 8; u++) {
                __half2* p = (__half2*)&rvh[u];
                float2 f0 = __half22float2(p[0]);
                float2 f1 = __half22float2(p[1]);
                *(float4*)(Vd + base + u * 32) = make_float4(f0.x, f0.y, f1.x, f1.y);
            }
        };
        auto compute2 = [&](int buf, int j0) {
            const float* Vd = Uf + buf * 8448;
#pragma unroll
            for (int ks = 0; ks < 2; ks++) {
                const int kk = ks * 16;
                uint32_t af[2][4];
#pragma unroll
                for (int mt = 0; mt < 2; mt++) {
                    int r0 = (wm + mt * 16 + g) * 260 + j0 + kk + tg * 2;
                    float2 p0 = *(const float2*)(S + r0);
                    float2 p1 = *(const float2*)(S + r0 + 8 * 260);
                    float2 p2 = *(const float2*)(S + r0 + 8);
                    float2 p3 = *(const float2*)(S + r0 + 8 * 260 + 8);
                    af[mt][0] = h2(p0.x, p0.y);
                    af[mt][1] = h2(p1.x, p1.y);
                    af[mt][2] = h2(p2.x, p2.y);
                    af[mt][3] = h2(p3.x, p3.y);
                }
#pragma unroll
                for (int nt = 0; nt < 8; nt++) {
                    int col = wn + nt * 8 + g;
                    int jr = kk + tg * 2;
                    uint32_t b0 = h2(Vd[jr * 264 + col],       Vd[(jr + 1) * 264 + col]);
                    uint32_t b1 = h2(Vd[(jr + 8) * 264 + col], Vd[(jr + 9) * 264 + col]);
#pragma unroll
                    for (int mt = 0; mt < 2; mt++)
                        mma16(acc2[mt][nt], af[mt][0], af[mt][1], af[mt][2], af[mt][3], b0, b1);
                }
            }
        };

        ldv(0); stv(0); __syncthreads();
        for (int t = 0; t < 8; t++) {
            if (t + 1 < 8) ldv((t + 1) * 32);
            compute2(t & 1, t * 32);
            if (t + 1 < 8) stv((t + 1) & 1);
            __syncthreads();
        }

#pragma unroll
        for (int mt = 0; mt < 2; mt++) {
            int row = wm + mt * 16 + g;
#pragma unroll
            for (int nt = 0; nt < 8; nt++) {
                int col = d0 + wn + nt * 8 + tg * 2;
                *(uint32_t*)(outbase + (size_t)row * 512 + col) =
                    h2(acc2[mt][nt][0], acc2[mt][nt][1]);
                *(uint32_t*)(outbase + (size_t)(row + 8) * 512 + col) =
                    h2(acc2[mt][nt][2], acc2[mt][nt][3]);
            }
        }
    }
}

// ---------------------------------------------------------------------------
extern "C" void kernel_launch(void* const* d_in, const int* in_sizes, int n_in,
                              void* d_out, int out_size)
{
    const float* x     = (const float*)d_in[0];   // (4, 8192, 512)
    const float* w_qkv = (const float*)d_in[1];   // (1536, 512) — V rows dead (ref bug)
    const float* w_out = (const float*)d_in[2];   // (512, 512)
    const float* b_out = (const float*)d_in[3];   // (512,)
    float* out = (float*)d_out;

    __half* qkbuf = nullptr;
    __half* attbuf = nullptr;
    cudaGetSymbolAddress((void**)&qkbuf, g_qk);
    cudaGetSymbolAddress((void**)&attbuf, g_att);

    const int gemm_smem = 2 * GSTG;                                    // 40960 B
    const int p1 = 2 * A1B;                                            // 51200 B
    const int p2 = 2 * 8448 * 4;                                       // 67584 B
    const int attn_smem = 64 * 260 * 4 + (p1 > p2 ? p1 : p2);          // 134144 B
    cudaFuncSetAttribute(gemm_f16<false, true>,
                         cudaFuncAttributeMaxDynamicSharedMemorySize, gemm_smem);
    cudaFuncSetAttribute(gemm_f16<true, false>,
                         cudaFuncAttributeMaxDynamicSharedMemorySize, gemm_smem);
    cudaFuncSetAttribute(attn_f16, cudaFuncAttributeMaxDynamicSharedMemorySize, attn_smem);

    // 1) Q,K projection: [32768,512] @ [1024,512]^T -> g_qk (fp16)
    dim3 g1(1024 / 128, MTOT / 128);
    gemm_f16<false, true><<<g1, 256, gemm_smem>>>(x, w_qkv, nullptr, qkbuf, MTOT, 1024, 512);

    // 2) Windowed attention (V := K per reference bug) -> g_att (fp16)
    attn_f16<<<512, 256, attn_smem>>>(qkbuf, attbuf);

    // 3) Output projection + bias: [32768,512](fp16) @ [512,512]^T -> out (fp32)
    dim3 g3(512 / 128, MTOT / 128);
    gemm_f16<true, false><<<g3, 256, gemm_smem>>>(attbuf, w_out, b_out, out, MTOT, 512, 512);
}

// round 9
// speedup vs baseline: 4.5755x; 1.0043x over previous
#include <cuda_runtime.h>
#include <cuda_fp16.h>
#include <cstdint>
#include <cstddef>

// B=4, N=8192, DIN=512, DINNER=512, DOUT=512, W=128 -> 64 windows/batch, pad=0
#define MTOT 32768

// Scratch (alloc-guard-safe __device__ globals), fp16
__device__ __half g_qk[(size_t)MTOT * 1024];   // [m][0:512]=Q, [m][512:1024]=K
__device__ __half g_att[(size_t)MTOT * 512];   // attention output

__device__ __forceinline__ uint32_t h2(float a, float b) {
    __half2 h = __floats2half2_rn(a, b);
    return *(uint32_t*)&h;
}
__device__ __forceinline__ uint32_t smem_u32(const void* p) {
    uint32_t a;
    asm("{ .reg .u64 t; cvta.to.shared.u64 t, %1; cvt.u32.u64 %0, t; }" : "=r"(a) : "l"(p));
    return a;
}
// fp16 mma m16n8k16, fp32 accumulate
__device__ __forceinline__ void mma16(float* c, uint32_t a0, uint32_t a1, uint32_t a2, uint32_t a3,
                                      uint32_t b0, uint32_t b1) {
    asm volatile("mma.sync.aligned.m16n8k16.row.col.f32.f16.f16.f32 "
                 "{%0,%1,%2,%3}, {%4,%5,%6,%7}, {%8,%9}, {%0,%1,%2,%3};"
                 : "+f"(c[0]), "+f"(c[1]), "+f"(c[2]), "+f"(c[3])
                 : "r"(a0), "r"(a1), "r"(a2), "r"(a3), "r"(b0), "r"(b1));
}
__device__ __forceinline__ void ldsm4(uint32_t* r, uint32_t addr) {
    asm volatile("ldmatrix.sync.aligned.m8n8.x4.shared.b16 {%0,%1,%2,%3}, [%4];"
                 : "=r"(r[0]), "=r"(r[1]), "=r"(r[2]), "=r"(r[3]) : "r"(addr));
}

// ---------------------------------------------------------------------------
// GEMM: C[M,Nc] = A[M,K] @ B[Nc,K]^T (+bias). fp16 mma + ldmatrix fragments.
// 128x128x32 tiles dbl-buffered, SMEM half pitch 40 (80B rows).
// 8 warps = 4(m) x 2(n); warp tile 32x64. A may be half (AHALF), C may be half (OHALF).
// ---------------------------------------------------------------------------
#define GP 40                       // halves per SMEM row
#define GROWB 80                    // bytes per SMEM row
#define GSTG (128 * GROWB * 2)      // bytes per stage (A tile + B tile) = 20480

template<bool AHALF, bool OHALF>
__global__ __launch_bounds__(256, 2)
void gemm_f16(const void* __restrict__ Ap, const float* __restrict__ Bm,
              const float* __restrict__ bias, void* __restrict__ Cp,
              int M, int Nc, int K)
{
    extern __shared__ char shb[];
    const uint32_t sb = smem_u32(shb);

    const int tid = threadIdx.x;
    const int lane = tid & 31, wid = tid >> 5;
    const int g = lane >> 2, tg = lane & 3;
    const int wm = (wid >> 1) * 32;
    const int wn = (wid & 1) * 64;
    const int lr = tid >> 3, lc = (tid & 7) * 4;

    // ldmatrix per-lane addresses (byte offsets into a stage)
    uint32_t aaddr[2], baddr[4];
#pragma unroll
    for (int mt = 0; mt < 2; mt++) {
        int row = wm + mt * 16 + (lane & 7) + ((lane >> 3) & 1) * 8;
        aaddr[mt] = sb + row * GROWB + (lane >> 4) * 16;
    }
#pragma unroll
    for (int ntp = 0; ntp < 4; ntp++) {
        int row = wn + ntp * 16 + (lane & 7) + (lane >> 4) * 8;
        baddr[ntp] = sb + 128 * GROWB + row * GROWB + ((lane >> 3) & 1) * 16;
    }

    const float* Bb = Bm + (size_t)blockIdx.x * 128 * K;

    float acc[2][8][4];
#pragma unroll
    for (int mt = 0; mt < 2; mt++)
#pragma unroll
        for (int nt = 0; nt < 8; nt++)
#pragma unroll
            for (int q = 0; q < 4; q++) acc[mt][nt][q] = 0.f;

    uint32_t ha[4][2], hb[4][2];
    auto ldg = [&](int k0) {
        if (AHALF) {
            const __half* Ab = (const __half*)Ap + (size_t)blockIdx.y * 128 * K;
#pragma unroll
            for (int it = 0; it < 4; it++) {
                uint2 v = *(const uint2*)(Ab + (size_t)(lr + it * 32) * K + k0 + lc);
                ha[it][0] = v.x; ha[it][1] = v.y;
            }
        } else {
            const float* Ab = (const float*)Ap + (size_t)blockIdx.y * 128 * K;
#pragma unroll
            for (int it = 0; it < 4; it++) {
                float4 v = *(const float4*)(Ab + (size_t)(lr + it * 32) * K + k0 + lc);
                ha[it][0] = h2(v.x, v.y); ha[it][1] = h2(v.z, v.w);
            }
        }
#pragma unroll
        for (int it = 0; it < 4; it++) {
            float4 v = *(const float4*)(Bb + (size_t)(lr + it * 32) * K + k0 + lc);
            hb[it][0] = h2(v.x, v.y); hb[it][1] = h2(v.z, v.w);
        }
    };
    auto sts = [&](int buf) {
        uint32_t* Ad = (uint32_t*)(shb + buf * GSTG);
        uint32_t* Bd = Ad + 128 * (GP / 2);
#pragma unroll
        for (int it = 0; it < 4; it++) {
            int base = (lr + it * 32) * (GP / 2) + (tid & 7) * 2;
            *(uint2*)(Ad + base) = make_uint2(ha[it][0], ha[it][1]);
            *(uint2*)(Bd + base) = make_uint2(hb[it][0], hb[it][1]);
        }
    };
    auto compute = [&](int buf) {
        const uint32_t so = buf * GSTG;
#pragma unroll
        for (int ks = 0; ks < 2; ks++) {
            uint32_t af[2][4];
            ldsm4(af[0], aaddr[0] + so + ks * 32);
            ldsm4(af[1], aaddr[1] + so + ks * 32);
#pragma unroll
            for (int ntp = 0; ntp < 4; ntp++) {
                uint32_t bf[4];
                ldsm4(bf, baddr[ntp] + so + ks * 32);
#pragma unroll
                for (int mt = 0; mt < 2; mt++) {
                    mma16(acc[mt][ntp * 2],     af[mt][0], af[mt][1], af[mt][2], af[mt][3], bf[0], bf[1]);
                    mma16(acc[mt][ntp * 2 + 1], af[mt][0], af[mt][1], af[mt][2], af[mt][3], bf[2], bf[3]);
                }
            }
        }
    };

    ldg(0); sts(0); __syncthreads();
    const int T = K / 32;
    for (int t = 0; t < T; t++) {
        if (t + 1 < T) ldg((t + 1) * 32);
        compute(t & 1);
        if (t + 1 < T) sts((t + 1) & 1);
        __syncthreads();
    }

#pragma unroll
    for (int mt = 0; mt < 2; mt++) {
        int row = blockIdx.y * 128 + wm + mt * 16 + g;
#pragma unroll
        for (int nt = 0; nt < 8; nt++) {
            int col = blockIdx.x * 128 + wn + nt * 8 + tg * 2;
            float b0 = 0.f, b1 = 0.f;
            if (bias) { b0 = bias[col]; b1 = bias[col + 1]; }
            if (OHALF) {
                __half* C = (__half*)Cp;
                *(uint32_t*)(C + (size_t)row * Nc + col) =
                    h2(acc[mt][nt][0] + b0, acc[mt][nt][1] + b1);
                *(uint32_t*)(C + (size_t)(row + 8) * Nc + col) =
                    h2(acc[mt][nt][2] + b0, acc[mt][nt][3] + b1);
            } else {
                float* C = (float*)Cp;
                *(float2*)(C + (size_t)row * Nc + col) =
                    make_float2(acc[mt][nt][0] + b0, acc[mt][nt][1] + b1);
                *(float2*)(C + (size_t)(row + 8) * Nc + col) =
                    make_float2(acc[mt][nt][2] + b0, acc[mt][nt][3] + b1);
            }
        }
    }
}

// ---------------------------------------------------------------------------
// Windowed attention. 512 blocks: b * 64 windows * 2 half-windows.
// Q,K read as fp16 from g_qk (no conversion). Phase1 via ldmatrix fragments.
// Softmax fp32. O = P @ K2 (reference bug: V := K), output fp16 into g_att.
// ---------------------------------------------------------------------------
#define A1B (64 * GROWB + 256 * GROWB)    // bytes per phase-1 stage (Q + K) = 25600

__global__ __launch_bounds__(256)
void attn_f16(const __half* __restrict__ qk, __half* __restrict__ outa)
{
    extern __shared__ float sh[];
    float* S = sh;                                   // 64 x 260 fp32
    char*  Ub = (char*)(sh + 64 * 260);              // ph1: half Q/K dbl-buf; ph2: fp32 V dbl-buf
    float* Uf = sh + 64 * 260;
    const uint32_t sbU = smem_u32(Ub);

    const int tid = threadIdx.x;
    const int lane = tid & 31, wid = tid >> 5;
    const int g = lane >> 2, tg = lane & 3;
    const int wm = (wid >> 2) * 32;
    const int wn = (wid & 3) * 64;

    const int z = blockIdx.x;
    const int b = z >> 7, r = z & 127, wb = r >> 1, half = r & 1;
    const __half* qbase = qk + ((size_t)(b * 8192 + wb * 128 + half * 64)) * 1024;
    const __half* kbase = qk + (size_t)b * 8192 * 1024 + 512;
    const int kn0 = wb * 128 - 128;

    const int lr = tid >> 3, lc = (tid & 7) * 4;

    // ---- Phase 1: S = Q @ K2^T (ldmatrix fragments)
    {
        uint32_t aaddr[2], baddr[4];
#pragma unroll
        for (int mt = 0; mt < 2; mt++) {
            int row = wm + mt * 16 + (lane & 7) + ((lane >> 3) & 1) * 8;
            aaddr[mt] = sbU + row * GROWB + (lane >> 4) * 16;
        }
#pragma unroll
        for (int ntp = 0; ntp < 4; ntp++) {
            int row = wn + ntp * 16 + (lane & 7) + (lane >> 4) * 8;
            baddr[ntp] = sbU + 64 * GROWB + row * GROWB + ((lane >> 3) & 1) * 16;
        }

        float acc[2][8][4];
#pragma unroll
        for (int mt = 0; mt < 2; mt++)
#pragma unroll
            for (int nt = 0; nt < 8; nt++)
#pragma unroll
                for (int q = 0; q < 4; q++) acc[mt][nt][q] = 0.f;

        uint2 hq[2], hk[8];
        auto ld1 = [&](int k0) {
#pragma unroll
            for (int it = 0; it < 2; it++)
                hq[it] = *(const uint2*)(qbase + (size_t)(lr + it * 32) * 1024 + k0 + lc);
#pragma unroll
            for (int it = 0; it < 8; it++) {
                int n = kn0 + lr + it * 32;
                hk[it] = make_uint2(0u, 0u);
                if (n >= 0)
                    hk[it] = *(const uint2*)(kbase + (size_t)n * 1024 + k0 + lc);
            }
        };
        auto st1 = [&](int buf) {
            uint32_t* Qd = (uint32_t*)(Ub + buf * A1B);
            uint32_t* Kd = Qd + 64 * (GP / 2);
#pragma unroll
            for (int it = 0; it < 2; it++)
                *(uint2*)(Qd + (lr + it * 32) * (GP / 2) + (tid & 7) * 2) = hq[it];
#pragma unroll
            for (int it = 0; it < 8; it++)
                *(uint2*)(Kd + (lr + it * 32) * (GP / 2) + (tid & 7) * 2) = hk[it];
        };
        auto compute1 = [&](int buf) {
            const uint32_t so = buf * A1B;
#pragma unroll
            for (int ks = 0; ks < 2; ks++) {
                uint32_t af[2][4];
                ldsm4(af[0], aaddr[0] + so + ks * 32);
                ldsm4(af[1], aaddr[1] + so + ks * 32);
#pragma unroll
                for (int ntp = 0; ntp < 4; ntp++) {
                    uint32_t bf[4];
                    ldsm4(bf, baddr[ntp] + so + ks * 32);
#pragma unroll
                    for (int mt = 0; mt < 2; mt++) {
                        mma16(acc[mt][ntp * 2],     af[mt][0], af[mt][1], af[mt][2], af[mt][3], bf[0], bf[1]);
                        mma16(acc[mt][ntp * 2 + 1], af[mt][0], af[mt][1], af[mt][2], af[mt][3], bf[2], bf[3]);
                    }
                }
            }
        };

        ld1(0); st1(0); __syncthreads();
        for (int t = 0; t < 16; t++) {
            if (t + 1 < 16) ld1((t + 1) * 32);
            compute1(t & 1);
            if (t + 1 < 16) st1((t + 1) & 1);
            __syncthreads();
        }

        const float scale = 0.044194173824159216f;  // 512^-0.5
#pragma unroll
        for (int mt = 0; mt < 2; mt++) {
#pragma unroll
            for (int nt = 0; nt < 8; nt++) {
                int row0 = wm + mt * 16 + g;
                int col = wn + nt * 8 + tg * 2;
#pragma unroll
                for (int hh = 0; hh < 2; hh++) {
                    int row = row0 + hh * 8;
                    int lim = half * 64 + row + 128;
                    float v0 = acc[mt][nt][hh * 2 + 0] * scale;
                    float v1 = acc[mt][nt][hh * 2 + 1] * scale;
                    S[row * 260 + col] = (col > lim) ? -1e30f : v0;
                    S[row * 260 + col + 1] = (col + 1 > lim) ? -1e30f : v1;
                }
            }
        }
    }
    __syncthreads();

    // ---- Softmax (fp32; P stays fp32 in S)
    {
        int row = tid >> 2, l4 = tid & 3;
        float m = -1e30f;
        for (int c = l4; c < 256; c += 4) m = fmaxf(m, S[row * 260 + c]);
        m = fmaxf(m, __shfl_xor_sync(0xffffffffu, m, 1));
        m = fmaxf(m, __shfl_xor_sync(0xffffffffu, m, 2));
        float s = 0.f;
        for (int c = l4; c < 256; c += 4) {
            float e = __expf(S[row * 260 + c] - m);
            S[row * 260 + c] = e;
            s += e;
        }
        s += __shfl_xor_sync(0xffffffffu, s, 1);
        s += __shfl_xor_sync(0xffffffffu, s, 2);
        float inv = 1.f / s;
        for (int c = l4; c < 256; c += 4) S[row * 260 + c] *= inv;
    }
    __syncthreads();

    // ---- Phase 2: O = P @ V  (V := K rows, reference bug). V fp32 in SMEM.
    __half* outbase = outa + ((size_t)(b * 8192 + wb * 128 + half * 64)) * 512;
    const int vr = tid >> 3;
    const int vc = (tid & 7) * 4;

    for (int d0 = 0; d0 < 512; d0 += 256) {
        float acc2[2][8][4];
#pragma unroll
        for (int mt = 0; mt < 2; mt++)
#pragma unroll
            for (int nt = 0; nt < 8; nt++)
#pragma unroll
                for (int q = 0; q < 4; q++) acc2[mt][nt][q] = 0.f;

        uint2 rvh[8];
        auto ldv = [&](int j0) {
            int n = kn0 + j0 + vr;
#pragma unroll
            for (int u = 0; u < 8; u++) {
                rvh[u] = make_uint2(0u, 0u);
                if (n >= 0)
                    rvh[u] = *(const uint2*)(kbase + (size_t)n * 1024 + d0 + vc + u * 32);
            }
        };
        auto stv = [&](int buf) {
            float* Vd = Uf + buf * 8448;   // pitch 264 fp32 (j rows, d cols)
            int base = vr * 264 + vc;
#pragma unroll
            for (int u = 0; u < 8; u++) {
                __half2* p = (__half2*)&rvh[u];
                float2 f0 = __half22float2(p[0]);
                float2 f1 = __half22float2(p[1]);
                *(float4*)(Vd + base + u * 32) = make_float4(f0.x, f0.y, f1.x, f1.y);
            }
        };
        auto compute2 = [&](int buf, int j0) {
            const float* Vd = Uf + buf * 8448;
#pragma unroll
            for (int ks = 0; ks < 2; ks++) {
                const int kk = ks * 16;
                uint32_t af[2][4];
#pragma unroll
                for (int mt = 0; mt < 2; mt++) {
                    int r0 = (wm + mt * 16 + g) * 260 + j0 + kk + tg * 2;
                    float2 p0 = *(const float2*)(S + r0);
                    float2 p1 = *(const float2*)(S + r0 + 8 * 260);
                    float2 p2 = *(const float2*)(S + r0 + 8);
                    float2 p3 = *(const float2*)(S + r0 + 8 * 260 + 8);
                    af[mt][0] = h2(p0.x, p0.y);
                    af[mt][1] = h2(p1.x, p1.y);
                    af[mt][2] = h2(p2.x, p2.y);
                    af[mt][3] = h2(p3.x, p3.y);
                }
#pragma unroll
                for (int nt = 0; nt < 8; nt++) {
                    int col = wn + nt * 8 + g;
                    int jr = kk + tg * 2;
                    uint32_t b0 = h2(Vd[jr * 264 + col],       Vd[(jr + 1) * 264 + col]);
                    uint32_t b1 = h2(Vd[(jr + 8) * 264 + col], Vd[(jr + 9) * 264 + col]);
#pragma unroll
                    for (int mt = 0; mt < 2; mt++)
                        mma16(acc2[mt][nt], af[mt][0], af[mt][1], af[mt][2], af[mt][3], b0, b1);
                }
            }
        };

        ldv(0); stv(0); __syncthreads();
        for (int t = 0; t < 8; t++) {
            if (t + 1 < 8) ldv((t + 1) * 32);
            compute2(t & 1, t * 32);
            if (t + 1 < 8) stv((t + 1) & 1);
            __syncthreads();
        }

#pragma unroll
        for (int mt = 0; mt < 2; mt++) {
            int row = wm + mt * 16 + g;
#pragma unroll
            for (int nt = 0; nt < 8; nt++) {
                int col = d0 + wn + nt * 8 + tg * 2;
                *(uint32_t*)(outbase + (size_t)row * 512 + col) =
                    h2(acc2[mt][nt][0], acc2[mt][nt][1]);
                *(uint32_t*)(outbase + (size_t)(row + 8) * 512 + col) =
                    h2(acc2[mt][nt][2], acc2[mt][nt][3]);
            }
        }
    }
}

// ---------------------------------------------------------------------------
extern "C" void kernel_launch(void* const* d_in, const int* in_sizes, int n_in,
                              void* d_out, int out_size)
{
    const float* x     = (const float*)d_in[0];   // (4, 8192, 512)
    const float* w_qkv = (const float*)d_in[1];   // (1536, 512) — V rows dead (ref bug)
    const float* w_out = (const float*)d_in[2];   // (512, 512)
    const float* b_out = (const float*)d_in[3];   // (512,)
    float* out = (float*)d_out;

    __half* qkbuf = nullptr;
    __half* attbuf = nullptr;
    cudaGetSymbolAddress((void**)&qkbuf, g_qk);
    cudaGetSymbolAddress((void**)&attbuf, g_att);

    const int gemm_smem = 2 * GSTG;                                    // 40960 B
    const int p1 = 2 * A1B;                                            // 51200 B
    const int p2 = 2 * 8448 * 4;                                       // 67584 B
    const int attn_smem = 64 * 260 * 4 + (p1 > p2 ? p1 : p2);          // 134144 B
    cudaFuncSetAttribute(gemm_f16<false, true>,
                         cudaFuncAttributeMaxDynamicSharedMemorySize, gemm_smem);
    cudaFuncSetAttribute(gemm_f16<true, false>,
                         cudaFuncAttributeMaxDynamicSharedMemorySize, gemm_smem);
    cudaFuncSetAttribute(attn_f16, cudaFuncAttributeMaxDynamicSharedMemorySize, attn_smem);

    // 1) Q,K projection: [32768,512] @ [1024,512]^T -> g_qk (fp16)
    dim3 g1(1024 / 128, MTOT / 128);
    gemm_f16<false, true><<<g1, 256, gemm_smem>>>(x, w_qkv, nullptr, qkbuf, MTOT, 1024, 512);

    // 2) Windowed attention (V := K per reference bug) -> g_att (fp16)
    attn_f16<<<512, 256, attn_smem>>>(qkbuf, attbuf);

    // 3) Output projection + bias: [32768,512](fp16) @ [512,512]^T -> out (fp32)
    dim3 g3(512 / 128, MTOT / 128);
    gemm_f16<true, false><<<g3, 256, gemm_smem>>>(attbuf, w_out, b_out, out, MTOT, 512, 512);
}

// round 10
// speedup vs baseline: 5.4617x; 1.1937x over previous
#include <cuda_runtime.h>
#include <cuda_fp16.h>
#include <cstdint>
#include <cstddef>

// B=4, N=8192, DIN=512, DINNER=512, DOUT=512, W=128 -> 64 windows/batch, pad=0
#define MTOT 32768

// Scratch (alloc-guard-safe __device__ globals), all fp16
__device__ __half g_x[(size_t)MTOT * 512];     // x converted to half
__device__ __half g_wqk[(size_t)1024 * 512];   // w_qkv rows 0:1024 (Q,K) as half
__device__ __half g_wout[(size_t)512 * 512];   // w_out as half
__device__ __half g_qk[(size_t)MTOT * 1024];   // [m][0:512]=Q, [m][512:1024]=K
__device__ __half g_att[(size_t)MTOT * 512];   // attention output

__device__ __forceinline__ uint32_t h2(float a, float b) {
    __half2 h = __floats2half2_rn(a, b);
    return *(uint32_t*)&h;
}
__device__ __forceinline__ uint32_t smem_u32(const void* p) {
    uint32_t a;
    asm("{ .reg .u64 t; cvta.to.shared.u64 t, %1; cvt.u32.u64 %0, t; }" : "=r"(a) : "l"(p));
    return a;
}
__device__ __forceinline__ void mma16(float* c, uint32_t a0, uint32_t a1, uint32_t a2, uint32_t a3,
                                      uint32_t b0, uint32_t b1) {
    asm volatile("mma.sync.aligned.m16n8k16.row.col.f32.f16.f16.f32 "
                 "{%0,%1,%2,%3}, {%4,%5,%6,%7}, {%8,%9}, {%0,%1,%2,%3};"
                 : "+f"(c[0]), "+f"(c[1]), "+f"(c[2]), "+f"(c[3])
                 : "r"(a0), "r"(a1), "r"(a2), "r"(a3), "r"(b0), "r"(b1));
}
__device__ __forceinline__ void ldsm4(uint32_t* r, uint32_t addr) {
    asm volatile("ldmatrix.sync.aligned.m8n8.x4.shared.b16 {%0,%1,%2,%3}, [%4];"
                 : "=r"(r[0]), "=r"(r[1]), "=r"(r[2]), "=r"(r[3]) : "r"(addr));
}
__device__ __forceinline__ void ldsm4t(uint32_t* r, uint32_t addr) {
    asm volatile("ldmatrix.sync.aligned.m8n8.x4.trans.shared.b16 {%0,%1,%2,%3}, [%4];"
                 : "=r"(r[0]), "=r"(r[1]), "=r"(r[2]), "=r"(r[3]) : "r"(addr));
}
__device__ __forceinline__ void cpa16(uint32_t dst, const void* src, uint32_t sz) {
    asm volatile("cp.async.cg.shared.global [%0], [%1], 16, %2;"
                 :: "r"(dst), "l"(src), "r"(sz) : "memory");
}
__device__ __forceinline__ void cpa_commit() { asm volatile("cp.async.commit_group;" ::: "memory"); }
__device__ __forceinline__ void cpa_wait2()  { asm volatile("cp.async.wait_group 2;" ::: "memory"); }

// ---------------------------------------------------------------------------
// fp32 -> fp16 bulk convert (n % 8 == 0)
// ---------------------------------------------------------------------------
__global__ __launch_bounds__(256)
void f2h_kernel(const float* __restrict__ src, __half* __restrict__ dst, int n)
{
    int i = (blockIdx.x * 256 + threadIdx.x) * 8;
    if (i < n) {
        float4 a = *(const float4*)(src + i);
        float4 b = *(const float4*)(src + i + 4);
        *(uint4*)(dst + i) = make_uint4(h2(a.x, a.y), h2(a.z, a.w),
                                        h2(b.x, b.y), h2(b.z, b.w));
    }
}

// ---------------------------------------------------------------------------
// GEMM: C[M,Nc] = A[M,K] @ B[Nc,K]^T (+bias), A,B fp16 K-major.
// 128x128x32 tiles, 4-stage cp.async pipeline, ldmatrix fragments.
// 8 warps = 4(m) x 2(n); warp tile 32x64.
// ---------------------------------------------------------------------------
#define GROWB 80                      // bytes per SMEM row (40 halves; 5 mod 8 -> LDSM clean)
#define GSTGB (256 * GROWB)           // per stage: A(128 rows) + B(128 rows) = 20480 B

template<bool OHALF>
__global__ __launch_bounds__(256, 2)
void gemm_h(const __half* __restrict__ A, const __half* __restrict__ Bm,
            const float* __restrict__ bias, void* __restrict__ Cp,
            int M, int Nc, int K)
{
    extern __shared__ char shb[];
    const uint32_t sb = smem_u32(shb);
    const int tid = threadIdx.x, lane = tid & 31, wid = tid >> 5;
    const int g = lane >> 2, tg = lane & 3;
    const int wm = (wid >> 1) * 32, wn = (wid & 1) * 64;

    const __half* Ab = A + (size_t)blockIdx.y * 128 * K;
    const __half* Bb = Bm + (size_t)blockIdx.x * 128 * K;
    const int crow = tid >> 1, cc = (tid & 1) * 32;      // cp.async: row + 32B half-row
    const char* ag0 = (const char*)(Ab + (size_t)crow * K) + cc;
    const char* bg0 = (const char*)(Bb + (size_t)crow * K) + cc;

    uint32_t aoff[2], boff[4];
#pragma unroll
    for (int mt = 0; mt < 2; mt++)
        aoff[mt] = (wm + mt * 16 + (lane & 7) + ((lane >> 3) & 1) * 8) * GROWB + (lane >> 4) * 16;
#pragma unroll
    for (int ntp = 0; ntp < 4; ntp++)
        boff[ntp] = 128 * GROWB + (wn + ntp * 16 + (lane & 7) + (lane >> 4) * 8) * GROWB
                    + ((lane >> 3) & 1) * 16;

    const int T = K / 32;
    auto issue = [&](int t) {
        if (t < T) {
            uint32_t s = sb + (t & 3) * GSTGB;
            uint32_t as = s + crow * GROWB + cc;
            uint32_t bs = s + 128 * GROWB + crow * GROWB + cc;
            const char* ag = ag0 + t * 64;
            const char* bg = bg0 + t * 64;
            cpa16(as, ag, 16);       cpa16(as + 16, ag + 16, 16);
            cpa16(bs, bg, 16);       cpa16(bs + 16, bg + 16, 16);
        }
        cpa_commit();
    };

    float acc[2][8][4];
#pragma unroll
    for (int mt = 0; mt < 2; mt++)
#pragma unroll
        for (int nt = 0; nt < 8; nt++)
#pragma unroll
            for (int q = 0; q < 4; q++) acc[mt][nt][q] = 0.f;

    issue(0); issue(1); issue(2);
    for (int t = 0; t < T; t++) {
        cpa_wait2();
        __syncthreads();
        issue(t + 3);
        const uint32_t s = sb + (t & 3) * GSTGB;
#pragma unroll
        for (int ks = 0; ks < 2; ks++) {
            uint32_t af[2][4];
            ldsm4(af[0], s + aoff[0] + ks * 32);
            ldsm4(af[1], s + aoff[1] + ks * 32);
#pragma unroll
            for (int ntp = 0; ntp < 4; ntp++) {
                uint32_t bf[4];
                ldsm4(bf, s + boff[ntp] + ks * 32);
#pragma unroll
                for (int mt = 0; mt < 2; mt++) {
                    mma16(acc[mt][ntp * 2],     af[mt][0], af[mt][1], af[mt][2], af[mt][3], bf[0], bf[1]);
                    mma16(acc[mt][ntp * 2 + 1], af[mt][0], af[mt][1], af[mt][2], af[mt][3], bf[2], bf[3]);
                }
            }
        }
    }

#pragma unroll
    for (int mt = 0; mt < 2; mt++) {
        int row = blockIdx.y * 128 + wm + mt * 16 + g;
#pragma unroll
        for (int nt = 0; nt < 8; nt++) {
            int col = blockIdx.x * 128 + wn + nt * 8 + tg * 2;
            float b0 = 0.f, b1 = 0.f;
            if (bias) { b0 = bias[col]; b1 = bias[col + 1]; }
            if (OHALF) {
                __half* C = (__half*)Cp;
                *(uint32_t*)(C + (size_t)row * Nc + col) =
                    h2(acc[mt][nt][0] + b0, acc[mt][nt][1] + b1);
                *(uint32_t*)(C + (size_t)(row + 8) * Nc + col) =
                    h2(acc[mt][nt][2] + b0, acc[mt][nt][3] + b1);
            } else {
                float* C = (float*)Cp;
                *(float2*)(C + (size_t)row * Nc + col) =
                    make_float2(acc[mt][nt][0] + b0, acc[mt][nt][1] + b1);
                *(float2*)(C + (size_t)(row + 8) * Nc + col) =
                    make_float2(acc[mt][nt][2] + b0, acc[mt][nt][3] + b1);
            }
        }
    }
}

// ---------------------------------------------------------------------------
// Windowed attention. 512 blocks: b * 64 windows * 2 half-windows.
// Phase1: S = Q@K2^T via cp.async(4-stage) + ldmatrix.  Softmax fp32 -> P fp16 (Sh).
// Phase2: O = P@V with P via ldmatrix, V via cp.async + ldmatrix.trans (V := K, ref bug).
// ---------------------------------------------------------------------------
#define A1STGB (320 * GROWB)          // Q(64 rows) + K(256 rows) = 25600 B per stage
#define SHP    264                    // Sh/V pitch in halves (528 B; 33 mod 8 = 1 -> LDSM clean)
#define VSTGB  (32 * SHP * 2)         // 16896 B per V stage
#define SH_OFF (64 * 260 * 4)         // 66560
#define U_OFF  (SH_OFF + 64 * SHP * 2)// 100352
#define ATTN_SMEM (U_OFF + 4 * A1STGB)// 202752

__global__ __launch_bounds__(256)
void attn_h(const __half* __restrict__ qk, __half* __restrict__ outa)
{
    extern __shared__ char shb[];
    float* S = (float*)shb;                       // 64 x 260 fp32
    __half* Sh = (__half*)(shb + SH_OFF);         // 64 x 264 fp16 (P)
    const uint32_t sb = smem_u32(shb);
    const uint32_t sbSh = sb + SH_OFF;
    const uint32_t sbU = sb + U_OFF;

    const int tid = threadIdx.x;
    const int lane = tid & 31, wid = tid >> 5;
    const int g = lane >> 2, tg = lane & 3;
    const int wm = (wid >> 2) * 32;
    const int wn = (wid & 3) * 64;

    const int z = blockIdx.x;
    const int b = z >> 7, r = z & 127, wb = r >> 1, half = r & 1;
    const __half* qbase = qk + ((size_t)(b * 8192 + wb * 128 + half * 64)) * 1024;
    const __half* kbase = qk + (size_t)b * 8192 * 1024 + 512;
    const int kn0 = wb * 128 - 128;

    // ---- Phase 1: S = Q @ K2^T --------------------------------------------
    {
        const int qrow = tid >> 2, qc = (tid & 3) * 16;
        const char* qg0 = (const char*)(qbase + (size_t)qrow * 1024) + qc;
        const char* kg0[4]; uint32_t ksz[4]; int krow[4];
#pragma unroll
        for (int u = 0; u < 4; u++) {
            krow[u] = qrow + 64 * u;
            int n = kn0 + krow[u];
            ksz[u] = (n >= 0) ? 16u : 0u;
            kg0[u] = (const char*)(kbase + (size_t)(n >= 0 ? n : 0) * 1024) + qc;
        }

        uint32_t aoff[2], boff[4];
#pragma unroll
        for (int mt = 0; mt < 2; mt++)
            aoff[mt] = (wm + mt * 16 + (lane & 7) + ((lane >> 3) & 1) * 8) * GROWB + (lane >> 4) * 16;
#pragma unroll
        for (int ntp = 0; ntp < 4; ntp++)
            boff[ntp] = 64 * GROWB + (wn + ntp * 16 + (lane & 7) + (lane >> 4) * 8) * GROWB
                        + ((lane >> 3) & 1) * 16;

        auto issue1 = [&](int t) {
            if (t < 16) {
                uint32_t s = sbU + (t & 3) * A1STGB;
                cpa16(s + qrow * GROWB + qc, qg0 + t * 64, 16);
#pragma unroll
                for (int u = 0; u < 4; u++)
                    cpa16(s + (64 + krow[u]) * GROWB + qc, kg0[u] + t * 64, ksz[u]);
            }
            cpa_commit();
        };

        float acc[2][8][4];
#pragma unroll
        for (int mt = 0; mt < 2; mt++)
#pragma unroll
            for (int nt = 0; nt < 8; nt++)
#pragma unroll
                for (int q = 0; q < 4; q++) acc[mt][nt][q] = 0.f;

        issue1(0); issue1(1); issue1(2);
        for (int t = 0; t < 16; t++) {
            cpa_wait2();
            __syncthreads();
            issue1(t + 3);
            const uint32_t s = sbU + (t & 3) * A1STGB;
#pragma unroll
            for (int ks = 0; ks < 2; ks++) {
                uint32_t af[2][4];
                ldsm4(af[0], s + aoff[0] + ks * 32);
                ldsm4(af[1], s + aoff[1] + ks * 32);
#pragma unroll
                for (int ntp = 0; ntp < 4; ntp++) {
                    uint32_t bf[4];
                    ldsm4(bf, s + boff[ntp] + ks * 32);
#pragma unroll
                    for (int mt = 0; mt < 2; mt++) {
                        mma16(acc[mt][ntp * 2],     af[mt][0], af[mt][1], af[mt][2], af[mt][3], bf[0], bf[1]);
                        mma16(acc[mt][ntp * 2 + 1], af[mt][0], af[mt][1], af[mt][2], af[mt][3], bf[2], bf[3]);
                    }
                }
            }
        }

        const float scale = 0.044194173824159216f;  // 512^-0.5
#pragma unroll
        for (int mt = 0; mt < 2; mt++) {
#pragma unroll
            for (int nt = 0; nt < 8; nt++) {
                int row0 = wm + mt * 16 + g;
                int col = wn + nt * 8 + tg * 2;
#pragma unroll
                for (int hh = 0; hh < 2; hh++) {
                    int row = row0 + hh * 8;
                    int lim = half * 64 + row + 128;   // mask: col > qi+128
                    float v0 = acc[mt][nt][hh * 2 + 0] * scale;
                    float v1 = acc[mt][nt][hh * 2 + 1] * scale;
                    S[row * 260 + col]     = (col > lim)     ? -1e30f : v0;
                    S[row * 260 + col + 1] = (col + 1 > lim) ? -1e30f : v1;
                }
            }
        }
    }
    __syncthreads();

    // ---- Softmax (fp32), write P as fp16 into Sh ----------------------------
    {
        int row = tid >> 2, l4 = tid & 3;
        float m = -1e30f;
        for (int c = l4; c < 256; c += 4) m = fmaxf(m, S[row * 260 + c]);
        m = fmaxf(m, __shfl_xor_sync(0xffffffffu, m, 1));
        m = fmaxf(m, __shfl_xor_sync(0xffffffffu, m, 2));
        float s = 0.f;
        for (int c = l4; c < 256; c += 4) {
            float e = __expf(S[row * 260 + c] - m);
            S[row * 260 + c] = e;
            s += e;
        }
        s += __shfl_xor_sync(0xffffffffu, s, 1);
        s += __shfl_xor_sync(0xffffffffu, s, 2);
        float inv = 1.f / s;
        for (int c = l4; c < 256; c += 4)
            Sh[row * SHP + c] = __float2half_rn(S[row * 260 + c] * inv);
    }
    __syncthreads();

    // ---- Phase 2: O = P @ V (V := K rows) -----------------------------------
    __half* outbase = outa + ((size_t)(b * 8192 + wb * 128 + half * 64)) * 512;
    const int vrow = tid >> 3, vcb = (tid & 7) * 64;

    uint32_t poff[2];
#pragma unroll
    for (int mt = 0; mt < 2; mt++)
        poff[mt] = sbSh + (wm + mt * 16 + (lane & 7) + ((lane >> 3) & 1) * 8) * (SHP * 2)
                   + (lane >> 4) * 16;

    for (int d0 = 0; d0 < 512; d0 += 256) {
        float acc2[2][8][4];
#pragma unroll
        for (int mt = 0; mt < 2; mt++)
#pragma unroll
            for (int nt = 0; nt < 8; nt++)
#pragma unroll
                for (int q = 0; q < 4; q++) acc2[mt][nt][q] = 0.f;

        auto issue2 = [&](int t) {
            if (t < 8) {
                int n = kn0 + t * 32 + vrow;
                uint32_t sz = (n >= 0) ? 16u : 0u;
                const char* src = (const char*)(kbase + (size_t)(n >= 0 ? n : 0) * 1024 + d0) + vcb;
                uint32_t vd = sbU + (t & 3) * VSTGB + vrow * (SHP * 2) + vcb;
#pragma unroll
                for (int u = 0; u < 4; u++)
                    cpa16(vd + u * 16, src + u * 16, sz);
            }
            cpa_commit();
        };

        issue2(0); issue2(1); issue2(2);
        for (int t = 0; t < 8; t++) {
            cpa_wait2();
            __syncthreads();
            issue2(t + 3);
            const uint32_t vs = sbU + (t & 3) * VSTGB;
            const int j0 = t * 32;
#pragma unroll
            for (int ks = 0; ks < 2; ks++) {
                uint32_t af[2][4];
                ldsm4(af[0], poff[0] + (j0 + ks * 16) * 2);
                ldsm4(af[1], poff[1] + (j0 + ks * 16) * 2);
#pragma unroll
                for (int ntp = 0; ntp < 4; ntp++) {
                    uint32_t bf[4];
                    ldsm4t(bf, vs + (ks * 16 + (lane & 7) + ((lane >> 3) & 1) * 8) * (SHP * 2)
                               + (wn + ntp * 16 + (lane >> 4) * 8) * 2);
#pragma unroll
                    for (int mt = 0; mt < 2; mt++) {
                        mma16(acc2[mt][ntp * 2],     af[mt][0], af[mt][1], af[mt][2], af[mt][3], bf[0], bf[1]);
                        mma16(acc2[mt][ntp * 2 + 1], af[mt][0], af[mt][1], af[mt][2], af[mt][3], bf[2], bf[3]);
                    }
                }
            }
        }

#pragma unroll
        for (int mt = 0; mt < 2; mt++) {
            int row = wm + mt * 16 + g;
#pragma unroll
            for (int nt = 0; nt < 8; nt++) {
                int col = d0 + wn + nt * 8 + tg * 2;
                *(uint32_t*)(outbase + (size_t)row * 512 + col) =
                    h2(acc2[mt][nt][0], acc2[mt][nt][1]);
                *(uint32_t*)(outbase + (size_t)(row + 8) * 512 + col) =
                    h2(acc2[mt][nt][2], acc2[mt][nt][3]);
            }
        }
        __syncthreads();   // V buffers reused by next d0 prologue
    }
}

// ---------------------------------------------------------------------------
extern "C" void kernel_launch(void* const* d_in, const int* in_sizes, int n_in,
                              void* d_out, int out_size)
{
    const float* x     = (const float*)d_in[0];   // (4, 8192, 512)
    const float* w_qkv = (const float*)d_in[1];   // (1536, 512) — V rows dead (ref bug)
    const float* w_out = (const float*)d_in[2];   // (512, 512)
    const float* b_out = (const float*)d_in[3];   // (512,)
    float* out = (float*)d_out;

    __half *xbuf, *wqkbuf, *woutbuf, *qkbuf, *attbuf;
    cudaGetSymbolAddress((void**)&xbuf,   g_x);
    cudaGetSymbolAddress((void**)&wqkbuf, g_wqk);
    cudaGetSymbolAddress((void**)&woutbuf,g_wout);
    cudaGetSymbolAddress((void**)&qkbuf,  g_qk);
    cudaGetSymbolAddress((void**)&attbuf, g_att);

    const int gemm_smem = 4 * GSTGB;              // 81920 B (2 CTAs/SM)
    cudaFuncSetAttribute(gemm_h<true>,  cudaFuncAttributeMaxDynamicSharedMemorySize, gemm_smem);
    cudaFuncSetAttribute(gemm_h<false>, cudaFuncAttributeMaxDynamicSharedMemorySize, gemm_smem);
    cudaFuncSetAttribute(attn_h, cudaFuncAttributeMaxDynamicSharedMemorySize, ATTN_SMEM);

    // 0) fp32 -> fp16 conversions
    f2h_kernel<<<(MTOT * 512) / (256 * 8), 256>>>(x, xbuf, MTOT * 512);
    f2h_kernel<<<(1024 * 512) / (256 * 8), 256>>>(w_qkv, wqkbuf, 1024 * 512);
    f2h_kernel<<<(512 * 512) / (256 * 8), 256>>>(w_out, woutbuf, 512 * 512);

    // 1) Q,K projection: [32768,512] @ [1024,512]^T -> g_qk (fp16)
    dim3 g1(1024 / 128, MTOT / 128);
    gemm_h<true><<<g1, 256, gemm_smem>>>(xbuf, wqkbuf, nullptr, qkbuf, MTOT, 1024, 512);

    // 2) Windowed attention (V := K per reference bug) -> g_att (fp16)
    attn_h<<<512, 256, ATTN_SMEM>>>(qkbuf, attbuf);

    // 3) Output projection + bias: [32768,512](fp16) @ [512,512]^T -> out (fp32)
    dim3 g3(512 / 128, MTOT / 128);
    gemm_h<false><<<g3, 256, gemm_smem>>>(attbuf, woutbuf, b_out, out, MTOT, 512, 512);
}